// round 1
// baseline (speedup 1.0000x reference)
#include <cuda_runtime.h>
#include <math.h>

#define B_ 2
#define N_ 4096
#define E_ 1024
#define R_ 128
#define H_ 8
#define ROWS_ (B_*N_)   // 8192

// ---------------- scratch (static device allocations; no cudaMalloc) -------
__device__ float g_q   [ROWS_*E_];
__device__ float g_k   [ROWS_*E_];
__device__ float g_v   [ROWS_*E_];
__device__ float g_beta[ROWS_*E_];
__device__ float g_gate[ROWS_*E_];
__device__ float g_o   [ROWS_*E_];
__device__ float g_t2  [ROWS_*E_];
__device__ float g_u   [ROWS_*R_];
__device__ float g_fg  [B_*H_*N_];

// ---------------- activation helpers ---------------------------------------
template<int ACT>
__device__ __forceinline__ float actf(float x) {
    if (ACT == 1) return x * (1.f / (1.f + __expf(-x)));   // silu
    if (ACT == 2) return 1.f / (1.f + __expf(-x));          // sigmoid
    return x;
}

// ---------------- generic fp32 NT GEMM: C[m,n] = act(sum_k A[m,k]*W[n,k]) ---
// M, Nc multiples of 128; K multiple of 8. 256 threads, 128x128 tile, 8x8/thr.
template<int ACT>
__global__ void gemm_nt(const float* __restrict__ A, const float* __restrict__ W,
                        float* __restrict__ C, int M, int Nc, int K)
{
    __shared__ alignas(16) float As[8][128];
    __shared__ alignas(16) float Ws[8][128];
    const int t  = threadIdx.x;
    const int bm = blockIdx.y, bn = blockIdx.x;
    const int tm = t >> 4, tn = t & 15;
    const int arow = t >> 1;
    const int acol = (t & 1) << 2;

    const float* Ap = A + (size_t)(bm * 128 + arow) * K + acol;
    const float* Wp = W + (size_t)(bn * 128 + arow) * K + acol;

    float acc[8][8];
#pragma unroll
    for (int i = 0; i < 8; i++)
#pragma unroll
        for (int j = 0; j < 8; j++) acc[i][j] = 0.f;

    for (int kt = 0; kt < K; kt += 8) {
        const float4 av = *reinterpret_cast<const float4*>(Ap + kt);
        const float4 wv = *reinterpret_cast<const float4*>(Wp + kt);
        __syncthreads();
        As[acol + 0][arow] = av.x; As[acol + 1][arow] = av.y;
        As[acol + 2][arow] = av.z; As[acol + 3][arow] = av.w;
        Ws[acol + 0][arow] = wv.x; Ws[acol + 1][arow] = wv.y;
        Ws[acol + 2][arow] = wv.z; Ws[acol + 3][arow] = wv.w;
        __syncthreads();
#pragma unroll
        for (int kk = 0; kk < 8; kk++) {
            float ra[8], rb[8];
            *reinterpret_cast<float4*>(&ra[0]) = *reinterpret_cast<const float4*>(&As[kk][tm * 8]);
            *reinterpret_cast<float4*>(&ra[4]) = *reinterpret_cast<const float4*>(&As[kk][tm * 8 + 4]);
            *reinterpret_cast<float4*>(&rb[0]) = *reinterpret_cast<const float4*>(&Ws[kk][tn * 8]);
            *reinterpret_cast<float4*>(&rb[4]) = *reinterpret_cast<const float4*>(&Ws[kk][tn * 8 + 4]);
#pragma unroll
            for (int i = 0; i < 8; i++)
#pragma unroll
                for (int j = 0; j < 8; j++)
                    acc[i][j] = fmaf(ra[i], rb[j], acc[i][j]);
        }
    }

#pragma unroll
    for (int i = 0; i < 8; i++) {
        float* cp = C + (size_t)(bm * 128 + tm * 8 + i) * Nc + bn * 128 + tn * 8;
        float4 o0, o1;
        o0.x = actf<ACT>(acc[i][0]); o0.y = actf<ACT>(acc[i][1]);
        o0.z = actf<ACT>(acc[i][2]); o0.w = actf<ACT>(acc[i][3]);
        o1.x = actf<ACT>(acc[i][4]); o1.y = actf<ACT>(acc[i][5]);
        o1.z = actf<ACT>(acc[i][6]); o1.w = actf<ACT>(acc[i][7]);
        *reinterpret_cast<float4*>(cp)     = o0;
        *reinterpret_cast<float4*>(cp + 4) = o1;
    }
}

// ---------------- f projection + decay gate ---------------------------------
// fg[b,h,n] = lb_h + (1-lb_h)*sigmoid(x_row . Wf[h])   (stored directly; the
// recurrence multiplies by fg == exp(log(fg)))
__global__ void fdecay_kernel(const float* __restrict__ x, const float* __restrict__ Wf,
                              const float* __restrict__ llb, float* __restrict__ fgout)
{
    const int row  = blockIdx.x;                 // 0..ROWS_-1
    const int h    = threadIdx.x >> 5;           // 8 warps = 8 heads
    const int lane = threadIdx.x & 31;
    const float* xr = x  + (size_t)row * E_;
    const float* wr = Wf + (size_t)h   * E_;
    float s = 0.f;
    for (int e = lane; e < E_; e += 32) s = fmaf(xr[e], wr[e], s);
#pragma unroll
    for (int m = 16; m; m >>= 1) s += __shfl_xor_sync(0xffffffffu, s, m);
    if (lane == 0) {
        const float lb  = __expf(llb[h]);
        const float fgv = lb + (1.f - lb) * (1.f / (1.f + __expf(-s)));
        const int b = row >> 12;                 // row / N_
        const int n = row & (N_ - 1);
        fgout[((size_t)b * H_ + h) * N_ + n] = fgv;
    }
}

// ---------------- householder: q -= 2*(q.bn)*bn, bn = beta/||beta|| ---------
// fused: q -= 2*(q.beta)/(beta.beta + 1e-12) * beta
__global__ void householder_kernel(float* __restrict__ q, const float* __restrict__ beta)
{
    const int row = blockIdx.x, t = threadIdx.x;      // 256 thr, 4 elems each
    const size_t base = (size_t)row * E_ + t * 4;
    const float4 b4 = *reinterpret_cast<const float4*>(beta + base);
    float4 q4 = *reinterpret_cast<float4*>(q + base);
    float ss = b4.x * b4.x + b4.y * b4.y + b4.z * b4.z + b4.w * b4.w;
    float dq = q4.x * b4.x + q4.y * b4.y + q4.z * b4.z + q4.w * b4.w;
#pragma unroll
    for (int m = 16; m; m >>= 1) {
        ss += __shfl_xor_sync(0xffffffffu, ss, m);
        dq += __shfl_xor_sync(0xffffffffu, dq, m);
    }
    __shared__ float sred[2][8];
    const int w = t >> 5, lane = t & 31;
    if (lane == 0) { sred[0][w] = ss; sred[1][w] = dq; }
    __syncthreads();
    float sst = 0.f, dqt = 0.f;
#pragma unroll
    for (int i = 0; i < 8; i++) { sst += sred[0][i]; dqt += sred[1][i]; }
    const float coef = 2.f * dqt / (sst + 1e-12f);
    q4.x -= coef * b4.x; q4.y -= coef * b4.y;
    q4.z -= coef * b4.z; q4.w -= coef * b4.w;
    *reinterpret_cast<float4*>(q + base) = q4;
}

// ---------------- GLA recurrence --------------------------------------------
// S_t = fg_t * S_{t-1} + k_t v_t^T ; o_t = scale * q_t @ S_t
// block = (b, h, vg): 16 v-columns; thread (col=t>>3, kg=t&7) owns 16 kk values
// of one column (kk = kg*4 + 32*j + l, conflict-free LDS.128 pattern).
__global__ void __launch_bounds__(128) gla_kernel(
    const float* __restrict__ q, const float* __restrict__ k,
    const float* __restrict__ v, const float* __restrict__ fg,
    float* __restrict__ o)
{
    const int bid = blockIdx.x;
    const int vg  = bid & 7;            // 8 v-splits of 16 cols
    const int bh  = bid >> 3;
    const int b   = bh >> 3, h = bh & 7;
    const int t   = threadIdx.x;
    const int col = t >> 3, kg = t & 7;

    __shared__ alignas(16) float sk[2][128];
    __shared__ alignas(16) float sq[2][128];
    __shared__ float sv[2][16];
    __shared__ float sg[2];

    const size_t rowbase = (size_t)b * N_ * E_ + (size_t)h * R_;
    const float* kb  = k + rowbase;
    const float* qb  = q + rowbase;
    const float* vb  = v + rowbase + vg * 16;
    const float* fgb = fg + (size_t)bh * N_;
    float* ob = o + rowbase + vg * 16 + col;

    float S[16];
#pragma unroll
    for (int i = 0; i < 16; i++) S[i] = 0.f;

    // prefetch step 0
    sk[0][t] = kb[t];
    sq[0][t] = qb[t];
    if (t < 16) sv[0][t] = vb[t];
    if (t == 0) sg[0] = fgb[0];
    __syncthreads();

    const float scale = rsqrtf((float)R_);
    for (int n = 0; n < N_; n++) {
        const int cur = n & 1, nxt = cur ^ 1;
        if (n + 1 < N_) {                       // prefetch next step
            const size_t off = (size_t)(n + 1) * E_;
            sk[nxt][t] = kb[off + t];
            sq[nxt][t] = qb[off + t];
            if (t < 16) sv[nxt][t] = vb[off + t];
            if (t == 0) sg[nxt] = fgb[n + 1];
        }
        const float eg   = sg[cur];
        const float vval = sv[cur][col];
        float acc = 0.f;
#pragma unroll
        for (int j = 0; j < 4; j++) {
            const float4 k4 = *reinterpret_cast<const float4*>(&sk[cur][kg * 4 + 32 * j]);
            const float4 q4 = *reinterpret_cast<const float4*>(&sq[cur][kg * 4 + 32 * j]);
            S[j*4+0] = fmaf(S[j*4+0], eg, k4.x * vval); acc = fmaf(q4.x, S[j*4+0], acc);
            S[j*4+1] = fmaf(S[j*4+1], eg, k4.y * vval); acc = fmaf(q4.y, S[j*4+1], acc);
            S[j*4+2] = fmaf(S[j*4+2], eg, k4.z * vval); acc = fmaf(q4.z, S[j*4+2], acc);
            S[j*4+3] = fmaf(S[j*4+3], eg, k4.w * vval); acc = fmaf(q4.w, S[j*4+3], acc);
        }
        acc += __shfl_xor_sync(0xffffffffu, acc, 1);
        acc += __shfl_xor_sync(0xffffffffu, acc, 2);
        acc += __shfl_xor_sync(0xffffffffu, acc, 4);
        if (kg == 0) ob[(size_t)n * E_] = acc * scale;
        __syncthreads();
    }
}

// ---------------- gate * o, then LayerNorm (weight only) --------------------
__global__ void gateln_kernel(const float* __restrict__ o, const float* __restrict__ gate,
                              const float* __restrict__ gamma, float* __restrict__ out)
{
    const int row = blockIdx.x, t = threadIdx.x;     // 256 thr, 4 elems each
    const size_t base = (size_t)row * E_ + t * 4;
    float4 ov = *reinterpret_cast<const float4*>(o + base);
    const float4 gv = *reinterpret_cast<const float4*>(gate + base);
    ov.x *= gv.x; ov.y *= gv.y; ov.z *= gv.z; ov.w *= gv.w;
    float s  = ov.x + ov.y + ov.z + ov.w;
    float s2 = ov.x * ov.x + ov.y * ov.y + ov.z * ov.z + ov.w * ov.w;
#pragma unroll
    for (int m = 16; m; m >>= 1) {
        s  += __shfl_xor_sync(0xffffffffu, s,  m);
        s2 += __shfl_xor_sync(0xffffffffu, s2, m);
    }
    __shared__ float sred[2][8];
    const int w = t >> 5, lane = t & 31;
    if (lane == 0) { sred[0][w] = s; sred[1][w] = s2; }
    __syncthreads();
    float st = 0.f, s2t = 0.f;
#pragma unroll
    for (int i = 0; i < 8; i++) { st += sred[0][i]; s2t += sred[1][i]; }
    const float mu  = st * (1.f / E_);
    const float var = s2t * (1.f / E_) - mu * mu;
    const float r   = rsqrtf(var + 1e-5f);
    const float4 gm = *reinterpret_cast<const float4*>(gamma + t * 4);
    float4 res;
    res.x = (ov.x - mu) * r * gm.x;
    res.y = (ov.y - mu) * r * gm.y;
    res.z = (ov.z - mu) * r * gm.z;
    res.w = (ov.w - mu) * r * gm.w;
    *reinterpret_cast<float4*>(out + base) = res;
}

// ---------------- launch ----------------------------------------------------
extern "C" void kernel_launch(void* const* d_in, const int* in_sizes, int n_in,
                              void* d_out, int out_size)
{
    (void)in_sizes; (void)n_in; (void)out_size;
    const float* x   = (const float*)d_in[0];
    const float* llb = (const float*)d_in[1];
    const float* Wq  = (const float*)d_in[2];
    const float* Wk  = (const float*)d_in[3];
    const float* Wv  = (const float*)d_in[4];
    const float* Wf  = (const float*)d_in[5];
    const float* Wb1 = (const float*)d_in[6];
    const float* Wb2 = (const float*)d_in[7];
    const float* Wg1 = (const float*)d_in[8];
    const float* Wg2 = (const float*)d_in[9];
    const float* gamma = (const float*)d_in[10];
    const float* Wo  = (const float*)d_in[11];
    float* out = (float*)d_out;

    float *q, *k, *v, *beta, *gate, *o, *t2, *u, *fg;
    cudaGetSymbolAddress((void**)&q,    g_q);
    cudaGetSymbolAddress((void**)&k,    g_k);
    cudaGetSymbolAddress((void**)&v,    g_v);
    cudaGetSymbolAddress((void**)&beta, g_beta);
    cudaGetSymbolAddress((void**)&gate, g_gate);
    cudaGetSymbolAddress((void**)&o,    g_o);
    cudaGetSymbolAddress((void**)&t2,   g_t2);
    cudaGetSymbolAddress((void**)&u,    g_u);
    cudaGetSymbolAddress((void**)&fg,   g_fg);

    const dim3 blk(256);
    const dim3 gBig(E_ / 128, ROWS_ / 128);   // (8, 64)
    const dim3 gLR (R_ / 128, ROWS_ / 128);   // (1, 64)

    // projections
    gemm_nt<1><<<gBig, blk>>>(x, Wq, q, ROWS_, E_, E_);   // q = silu(x Wq^T)
    gemm_nt<1><<<gBig, blk>>>(x, Wk, k, ROWS_, E_, E_);   // k = silu(x Wk^T)
    gemm_nt<0><<<gBig, blk>>>(x, Wv, v, ROWS_, E_, E_);   // v = x Wv^T
    fdecay_kernel<<<ROWS_, 256>>>(x, Wf, llb, fg);        // decay gate fg[b,h,n]

    // low-rank beta / gate paths (g_u reused sequentially)
    gemm_nt<0><<<gLR,  blk>>>(x, Wb1, u,    ROWS_, R_, E_);
    gemm_nt<1><<<gBig, blk>>>(u, Wb2, beta, ROWS_, E_, R_);  // beta = silu(u Wb2^T)
    gemm_nt<0><<<gLR,  blk>>>(x, Wg1, u,    ROWS_, R_, E_);
    gemm_nt<2><<<gBig, blk>>>(u, Wg2, gate, ROWS_, E_, R_);  // gate = sigmoid(...)

    // householder q-transform
    householder_kernel<<<ROWS_, 256>>>(q, beta);

    // gated linear attention recurrence
    gla_kernel<<<B_ * H_ * 8, 128>>>(q, k, v, fg, o);

    // gate + layernorm
    gateln_kernel<<<ROWS_, 256>>>(o, gate, gamma, t2);

    // output projection
    gemm_nt<0><<<gBig, blk>>>(t2, Wo, out, ROWS_, E_, E_);
}

// round 2
// speedup vs baseline: 1.4167x; 1.4167x over previous
#include <cuda_runtime.h>
#include <math.h>
#include <stdint.h>

#define B_ 2
#define N_ 4096
#define E_ 1024
#define R_ 128
#define H_ 8
#define ROWS_ (B_*N_)   // 8192

// ---------------- scratch (static device allocations; no cudaMalloc) -------
__device__ float g_q   [ROWS_*E_];
__device__ float g_k   [ROWS_*E_];
__device__ float g_v   [ROWS_*E_];
__device__ float g_beta[ROWS_*E_];
__device__ float g_gate[ROWS_*E_];
__device__ float g_o   [ROWS_*E_];
__device__ float g_t2  [ROWS_*E_];
__device__ float g_u   [ROWS_*R_];
__device__ float g_fg  [B_*H_*N_];

// ---------------- activation helpers ---------------------------------------
template<int ACT>
__device__ __forceinline__ float actf(float x) {
    if (ACT == 1) return x * (1.f / (1.f + __expf(-x)));   // silu
    if (ACT == 2) return 1.f / (1.f + __expf(-x));          // sigmoid
    return x;
}

__device__ __forceinline__ uint32_t f2tf32(float x) {
    uint32_t r;
    asm("cvt.rna.tf32.f32 %0, %1;" : "=r"(r) : "f"(x));
    return r;
}

__device__ __forceinline__ void mma_tf32(float c[4], const uint32_t a[4], const uint32_t b[2]) {
    asm volatile(
        "mma.sync.aligned.m16n8k8.row.col.f32.tf32.tf32.f32 "
        "{%0,%1,%2,%3}, {%4,%5,%6,%7}, {%8,%9}, {%0,%1,%2,%3};"
        : "+f"(c[0]), "+f"(c[1]), "+f"(c[2]), "+f"(c[3])
        : "r"(a[0]), "r"(a[1]), "r"(a[2]), "r"(a[3]), "r"(b[0]), "r"(b[1]));
}

// ---------------- tf32 tensor-core NT GEMM ----------------------------------
// C[m,n] = act(sum_k A[m,k]*W[n,k]); M,Nc mult of 128; K mult of 32.
// 256 thr = 8 warps (4m x 2n); warp tile 32x64; K-chunk 32 in smem (stride 36).
#define LDS_ 36
template<int ACT>
__global__ void __launch_bounds__(256, 2) gemm_tf32(
    const float* __restrict__ A, const float* __restrict__ W,
    float* __restrict__ C, int M, int Nc, int K)
{
    __shared__ uint32_t As[128 * LDS_];
    __shared__ uint32_t Ws[128 * LDS_];
    const int t    = threadIdx.x;
    const int warp = t >> 5, lane = t & 31;
    const int bm = blockIdx.y, bn = blockIdx.x;
    const int wm = (warp >> 1) * 32;      // warp m offset in tile
    const int wn = (warp & 1) * 64;       // warp n offset in tile
    const int gm = lane >> 2, gc = lane & 3;

    float acc[2][8][4];
#pragma unroll
    for (int i = 0; i < 2; i++)
#pragma unroll
        for (int j = 0; j < 8; j++)
#pragma unroll
            for (int l = 0; l < 4; l++) acc[i][j][l] = 0.f;

    const int ldr = t >> 1;               // 0..127
    const int ldc = (t & 1) * 16;         // 0 or 16
    const float* Ap = A + (size_t)(bm * 128 + ldr) * K + ldc;
    const float* Wp = W + (size_t)(bn * 128 + ldr) * K + ldc;

    for (int kt = 0; kt < K; kt += 32) {
        float4 a4[4], w4[4];
#pragma unroll
        for (int i = 0; i < 4; i++) {
            a4[i] = *reinterpret_cast<const float4*>(Ap + kt + i * 4);
            w4[i] = *reinterpret_cast<const float4*>(Wp + kt + i * 4);
        }
        __syncthreads();
#pragma unroll
        for (int i = 0; i < 4; i++) {
            uint4 av, wv;
            av.x = f2tf32(a4[i].x); av.y = f2tf32(a4[i].y);
            av.z = f2tf32(a4[i].z); av.w = f2tf32(a4[i].w);
            wv.x = f2tf32(w4[i].x); wv.y = f2tf32(w4[i].y);
            wv.z = f2tf32(w4[i].z); wv.w = f2tf32(w4[i].w);
            *reinterpret_cast<uint4*>(&As[ldr * LDS_ + ldc + i * 4]) = av;
            *reinterpret_cast<uint4*>(&Ws[ldr * LDS_ + ldc + i * 4]) = wv;
        }
        __syncthreads();
#pragma unroll
        for (int kk = 0; kk < 32; kk += 8) {
            uint32_t af[2][4];
#pragma unroll
            for (int mt = 0; mt < 2; mt++) {
                const int row = wm + mt * 16;
                af[mt][0] = As[(row + gm)     * LDS_ + kk + gc];
                af[mt][1] = As[(row + gm + 8) * LDS_ + kk + gc];
                af[mt][2] = As[(row + gm)     * LDS_ + kk + gc + 4];
                af[mt][3] = As[(row + gm + 8) * LDS_ + kk + gc + 4];
            }
            uint32_t bf[8][2];
#pragma unroll
            for (int nt = 0; nt < 8; nt++) {
                const int col = wn + nt * 8;
                bf[nt][0] = Ws[(col + gm) * LDS_ + kk + gc];
                bf[nt][1] = Ws[(col + gm) * LDS_ + kk + gc + 4];
            }
#pragma unroll
            for (int mt = 0; mt < 2; mt++)
#pragma unroll
                for (int nt = 0; nt < 8; nt++)
                    mma_tf32(acc[mt][nt], af[mt], bf[nt]);
        }
    }

    // epilogue: c0 at (gm, 2*gc), c1 (+0,+1), c2 (gm+8, 2*gc), c3 (+8,+1)
#pragma unroll
    for (int mt = 0; mt < 2; mt++) {
        const int row0 = bm * 128 + wm + mt * 16 + gm;
#pragma unroll
        for (int nt = 0; nt < 8; nt++) {
            const int col = bn * 128 + wn + nt * 8 + 2 * gc;
            float2 lo, hi;
            lo.x = actf<ACT>(acc[mt][nt][0]); lo.y = actf<ACT>(acc[mt][nt][1]);
            hi.x = actf<ACT>(acc[mt][nt][2]); hi.y = actf<ACT>(acc[mt][nt][3]);
            *reinterpret_cast<float2*>(C + (size_t)row0 * Nc + col)       = lo;
            *reinterpret_cast<float2*>(C + (size_t)(row0 + 8) * Nc + col) = hi;
        }
    }
}

// ---------------- f projection + decay gate ---------------------------------
__global__ void fdecay_kernel(const float* __restrict__ x, const float* __restrict__ Wf,
                              const float* __restrict__ llb, float* __restrict__ fgout)
{
    const int row  = blockIdx.x;
    const int h    = threadIdx.x >> 5;
    const int lane = threadIdx.x & 31;
    const float* xr = x  + (size_t)row * E_;
    const float* wr = Wf + (size_t)h   * E_;
    float s = 0.f;
    for (int e = lane; e < E_; e += 32) s = fmaf(xr[e], wr[e], s);
#pragma unroll
    for (int m = 16; m; m >>= 1) s += __shfl_xor_sync(0xffffffffu, s, m);
    if (lane == 0) {
        const float lb  = __expf(llb[h]);
        const float fgv = lb + (1.f - lb) * (1.f / (1.f + __expf(-s)));
        const int b = row >> 12;
        const int n = row & (N_ - 1);
        fgout[((size_t)b * H_ + h) * N_ + n] = fgv;
    }
}

// ---------------- householder: q -= 2*(q.beta)/(beta.beta+eps) * beta -------
__global__ void householder_kernel(float* __restrict__ q, const float* __restrict__ beta)
{
    const int row = blockIdx.x, t = threadIdx.x;
    const size_t base = (size_t)row * E_ + t * 4;
    const float4 b4 = *reinterpret_cast<const float4*>(beta + base);
    float4 q4 = *reinterpret_cast<float4*>(q + base);
    float ss = b4.x * b4.x + b4.y * b4.y + b4.z * b4.z + b4.w * b4.w;
    float dq = q4.x * b4.x + q4.y * b4.y + q4.z * b4.z + q4.w * b4.w;
#pragma unroll
    for (int m = 16; m; m >>= 1) {
        ss += __shfl_xor_sync(0xffffffffu, ss, m);
        dq += __shfl_xor_sync(0xffffffffu, dq, m);
    }
    __shared__ float sred[2][8];
    const int w = t >> 5, lane = t & 31;
    if (lane == 0) { sred[0][w] = ss; sred[1][w] = dq; }
    __syncthreads();
    float sst = 0.f, dqt = 0.f;
#pragma unroll
    for (int i = 0; i < 8; i++) { sst += sred[0][i]; dqt += sred[1][i]; }
    const float coef = 2.f * dqt / (sst + 1e-12f);
    q4.x -= coef * b4.x; q4.y -= coef * b4.y;
    q4.z -= coef * b4.z; q4.w -= coef * b4.w;
    *reinterpret_cast<float4*>(q + base) = q4;
}

// ---------------- GLA recurrence --------------------------------------------
__global__ void __launch_bounds__(128) gla_kernel(
    const float* __restrict__ q, const float* __restrict__ k,
    const float* __restrict__ v, const float* __restrict__ fg,
    float* __restrict__ o)
{
    const int bid = blockIdx.x;
    const int vg  = bid & 7;
    const int bh  = bid >> 3;
    const int b   = bh >> 3, h = bh & 7;
    const int t   = threadIdx.x;
    const int col = t >> 3, kg = t & 7;

    __shared__ alignas(16) float sk[2][128];
    __shared__ alignas(16) float sq[2][128];
    __shared__ float sv[2][16];
    __shared__ float sg[2];

    const size_t rowbase = (size_t)b * N_ * E_ + (size_t)h * R_;
    const float* kb  = k + rowbase;
    const float* qb  = q + rowbase;
    const float* vb  = v + rowbase + vg * 16;
    const float* fgb = fg + (size_t)bh * N_;
    float* ob = o + rowbase + vg * 16 + col;

    float S[16];
#pragma unroll
    for (int i = 0; i < 16; i++) S[i] = 0.f;

    sk[0][t] = kb[t];
    sq[0][t] = qb[t];
    if (t < 16) sv[0][t] = vb[t];
    if (t == 0) sg[0] = fgb[0];
    __syncthreads();

    const float scale = rsqrtf((float)R_);
    for (int n = 0; n < N_; n++) {
        const int cur = n & 1, nxt = cur ^ 1;
        if (n + 1 < N_) {
            const size_t off = (size_t)(n + 1) * E_;
            sk[nxt][t] = kb[off + t];
            sq[nxt][t] = qb[off + t];
            if (t < 16) sv[nxt][t] = vb[off + t];
            if (t == 0) sg[nxt] = fgb[n + 1];
        }
        const float eg   = sg[cur];
        const float vval = sv[cur][col];
        float acc = 0.f;
#pragma unroll
        for (int j = 0; j < 4; j++) {
            const float4 k4 = *reinterpret_cast<const float4*>(&sk[cur][kg * 4 + 32 * j]);
            const float4 q4 = *reinterpret_cast<const float4*>(&sq[cur][kg * 4 + 32 * j]);
            S[j*4+0] = fmaf(S[j*4+0], eg, k4.x * vval); acc = fmaf(q4.x, S[j*4+0], acc);
            S[j*4+1] = fmaf(S[j*4+1], eg, k4.y * vval); acc = fmaf(q4.y, S[j*4+1], acc);
            S[j*4+2] = fmaf(S[j*4+2], eg, k4.z * vval); acc = fmaf(q4.z, S[j*4+2], acc);
            S[j*4+3] = fmaf(S[j*4+3], eg, k4.w * vval); acc = fmaf(q4.w, S[j*4+3], acc);
        }
        acc += __shfl_xor_sync(0xffffffffu, acc, 1);
        acc += __shfl_xor_sync(0xffffffffu, acc, 2);
        acc += __shfl_xor_sync(0xffffffffu, acc, 4);
        if (kg == 0) ob[(size_t)n * E_] = acc * scale;
        __syncthreads();
    }
}

// ---------------- gate * o, then LayerNorm (weight only) --------------------
__global__ void gateln_kernel(const float* __restrict__ o, const float* __restrict__ gate,
                              const float* __restrict__ gamma, float* __restrict__ out)
{
    const int row = blockIdx.x, t = threadIdx.x;
    const size_t base = (size_t)row * E_ + t * 4;
    float4 ov = *reinterpret_cast<const float4*>(o + base);
    const float4 gv = *reinterpret_cast<const float4*>(gate + base);
    ov.x *= gv.x; ov.y *= gv.y; ov.z *= gv.z; ov.w *= gv.w;
    float s  = ov.x + ov.y + ov.z + ov.w;
    float s2 = ov.x * ov.x + ov.y * ov.y + ov.z * ov.z + ov.w * ov.w;
#pragma unroll
    for (int m = 16; m; m >>= 1) {
        s  += __shfl_xor_sync(0xffffffffu, s,  m);
        s2 += __shfl_xor_sync(0xffffffffu, s2, m);
    }
    __shared__ float sred[2][8];
    const int w = t >> 5, lane = t & 31;
    if (lane == 0) { sred[0][w] = s; sred[1][w] = s2; }
    __syncthreads();
    float st = 0.f, s2t = 0.f;
#pragma unroll
    for (int i = 0; i < 8; i++) { st += sred[0][i]; s2t += sred[1][i]; }
    const float mu  = st * (1.f / E_);
    const float var = s2t * (1.f / E_) - mu * mu;
    const float r   = rsqrtf(var + 1e-5f);
    const float4 gm = *reinterpret_cast<const float4*>(gamma + t * 4);
    float4 res;
    res.x = (ov.x - mu) * r * gm.x;
    res.y = (ov.y - mu) * r * gm.y;
    res.z = (ov.z - mu) * r * gm.z;
    res.w = (ov.w - mu) * r * gm.w;
    *reinterpret_cast<float4*>(out + base) = res;
}

// ---------------- launch ----------------------------------------------------
extern "C" void kernel_launch(void* const* d_in, const int* in_sizes, int n_in,
                              void* d_out, int out_size)
{
    (void)in_sizes; (void)n_in; (void)out_size;
    const float* x   = (const float*)d_in[0];
    const float* llb = (const float*)d_in[1];
    const float* Wq  = (const float*)d_in[2];
    const float* Wk  = (const float*)d_in[3];
    const float* Wv  = (const float*)d_in[4];
    const float* Wf  = (const float*)d_in[5];
    const float* Wb1 = (const float*)d_in[6];
    const float* Wb2 = (const float*)d_in[7];
    const float* Wg1 = (const float*)d_in[8];
    const float* Wg2 = (const float*)d_in[9];
    const float* gamma = (const float*)d_in[10];
    const float* Wo  = (const float*)d_in[11];
    float* out = (float*)d_out;

    float *q, *k, *v, *beta, *gate, *o, *t2, *u, *fg;
    cudaGetSymbolAddress((void**)&q,    g_q);
    cudaGetSymbolAddress((void**)&k,    g_k);
    cudaGetSymbolAddress((void**)&v,    g_v);
    cudaGetSymbolAddress((void**)&beta, g_beta);
    cudaGetSymbolAddress((void**)&gate, g_gate);
    cudaGetSymbolAddress((void**)&o,    g_o);
    cudaGetSymbolAddress((void**)&t2,   g_t2);
    cudaGetSymbolAddress((void**)&u,    g_u);
    cudaGetSymbolAddress((void**)&fg,   g_fg);

    const dim3 blk(256);
    const dim3 gBig(E_ / 128, ROWS_ / 128);   // (8, 64)
    const dim3 gLR (R_ / 128, ROWS_ / 128);   // (1, 64)

    // projections (tf32 tensor cores)
    gemm_tf32<1><<<gBig, blk>>>(x, Wq, q, ROWS_, E_, E_);
    gemm_tf32<1><<<gBig, blk>>>(x, Wk, k, ROWS_, E_, E_);
    gemm_tf32<0><<<gBig, blk>>>(x, Wv, v, ROWS_, E_, E_);
    fdecay_kernel<<<ROWS_, 256>>>(x, Wf, llb, fg);

    // low-rank beta / gate paths
    gemm_tf32<0><<<gLR,  blk>>>(x, Wb1, u,    ROWS_, R_, E_);
    gemm_tf32<1><<<gBig, blk>>>(u, Wb2, beta, ROWS_, E_, R_);
    gemm_tf32<0><<<gLR,  blk>>>(x, Wg1, u,    ROWS_, R_, E_);
    gemm_tf32<2><<<gBig, blk>>>(u, Wg2, gate, ROWS_, E_, R_);

    // householder q-transform
    householder_kernel<<<ROWS_, 256>>>(q, beta);

    // gated linear attention recurrence
    gla_kernel<<<B_ * H_ * 8, 128>>>(q, k, v, fg, o);

    // gate + layernorm
    gateln_kernel<<<ROWS_, 256>>>(o, gate, gamma, t2);

    // output projection
    gemm_tf32<0><<<gBig, blk>>>(t2, Wo, out, ROWS_, E_, E_);
}

// round 3
// speedup vs baseline: 1.4210x; 1.0031x over previous
#include <cuda_runtime.h>
#include <math.h>
#include <stdint.h>

#define B_ 2
#define N_ 4096
#define E_ 1024
#define R_ 128
#define H_ 8
#define ROWS_ (B_*N_)   // 8192

// ---------------- scratch (static device allocations; no cudaMalloc) -------
__device__ float g_q   [ROWS_*E_];
__device__ float g_k   [ROWS_*E_];
__device__ float g_v   [ROWS_*E_];
__device__ float g_beta[ROWS_*E_];
__device__ float g_gate[ROWS_*E_];
__device__ float g_o   [ROWS_*E_];
__device__ float g_t2  [ROWS_*E_];
__device__ float g_u   [ROWS_*R_];
__device__ float g_u2  [ROWS_*R_];
__device__ float g_fg  [B_*H_*N_];

// ---------------- helpers ----------------------------------------------------
__device__ __forceinline__ float act_rt(float x, int a) {
    if (a == 1) return x * (1.f / (1.f + __expf(-x)));   // silu
    if (a == 2) return 1.f / (1.f + __expf(-x));          // sigmoid
    return x;
}

__device__ __forceinline__ uint32_t f2tf32(float x) {
    uint32_t r;
    asm("cvt.rna.tf32.f32 %0, %1;" : "=r"(r) : "f"(x));
    return r;
}

__device__ __forceinline__ void mma_tf32(float c[4], const uint32_t a[4], const uint32_t b[2]) {
    asm volatile(
        "mma.sync.aligned.m16n8k8.row.col.f32.tf32.tf32.f32 "
        "{%0,%1,%2,%3}, {%4,%5,%6,%7}, {%8,%9}, {%0,%1,%2,%3};"
        : "+f"(c[0]), "+f"(c[1]), "+f"(c[2]), "+f"(c[3])
        : "r"(a[0]), "r"(a[1]), "r"(a[2]), "r"(a[3]), "r"(b[0]), "r"(b[1]));
}

struct GemmBatch {
    const float* A[3];
    const float* W[3];
    float*       C[3];
    int          act[3];
};

// ---------------- tf32 tensor-core NT GEMM (pipelined, batched via z) -------
// C[m,n] = act(sum_k A[m,k]*W[n,k]); M,Nc mult of 128; K mult of 32.
// 256 thr = 8 warps (4m x 2n); warp tile 32x64; K-chunk 32, register-staged.
#define LDS_ 36
__global__ void __launch_bounds__(256, 2) gemm_tf32(GemmBatch gb, int M, int Nc, int K)
{
    __shared__ uint32_t As[128 * LDS_];
    __shared__ uint32_t Ws[128 * LDS_];
    const int z = blockIdx.z;
    const float* __restrict__ A = gb.A[z];
    const float* __restrict__ W = gb.W[z];
    float* __restrict__ C = gb.C[z];
    const int ACT = gb.act[z];

    const int t    = threadIdx.x;
    const int warp = t >> 5, lane = t & 31;
    const int bm = blockIdx.y, bn = blockIdx.x;
    const int wm = (warp >> 1) * 32;
    const int wn = (warp & 1) * 64;
    const int gm = lane >> 2, gc = lane & 3;

    float acc[2][8][4];
#pragma unroll
    for (int i = 0; i < 2; i++)
#pragma unroll
        for (int j = 0; j < 8; j++)
#pragma unroll
            for (int l = 0; l < 4; l++) acc[i][j][l] = 0.f;

    const int ldr = t >> 1;
    const int ldc = (t & 1) * 16;
    const float* Ap = A + (size_t)(bm * 128 + ldr) * K + ldc;
    const float* Wp = W + (size_t)(bn * 128 + ldr) * K + ldc;

    float4 a4[4], w4[4];
#pragma unroll
    for (int i = 0; i < 4; i++) {            // prologue: chunk 0
        a4[i] = *reinterpret_cast<const float4*>(Ap + i * 4);
        w4[i] = *reinterpret_cast<const float4*>(Wp + i * 4);
    }

    for (int kt = 0; kt < K; kt += 32) {
        __syncthreads();
#pragma unroll
        for (int i = 0; i < 4; i++) {        // cvt + store staged chunk
            uint4 av, wv;
            av.x = f2tf32(a4[i].x); av.y = f2tf32(a4[i].y);
            av.z = f2tf32(a4[i].z); av.w = f2tf32(a4[i].w);
            wv.x = f2tf32(w4[i].x); wv.y = f2tf32(w4[i].y);
            wv.z = f2tf32(w4[i].z); wv.w = f2tf32(w4[i].w);
            *reinterpret_cast<uint4*>(&As[ldr * LDS_ + ldc + i * 4]) = av;
            *reinterpret_cast<uint4*>(&Ws[ldr * LDS_ + ldc + i * 4]) = wv;
        }
        __syncthreads();
        if (kt + 32 < K) {                   // issue loads for next chunk
#pragma unroll
            for (int i = 0; i < 4; i++) {
                a4[i] = *reinterpret_cast<const float4*>(Ap + kt + 32 + i * 4);
                w4[i] = *reinterpret_cast<const float4*>(Wp + kt + 32 + i * 4);
            }
        }
#pragma unroll
        for (int kk = 0; kk < 32; kk += 8) { // compute current chunk
            uint32_t af[2][4];
#pragma unroll
            for (int mt = 0; mt < 2; mt++) {
                const int row = wm + mt * 16;
                af[mt][0] = As[(row + gm)     * LDS_ + kk + gc];
                af[mt][1] = As[(row + gm + 8) * LDS_ + kk + gc];
                af[mt][2] = As[(row + gm)     * LDS_ + kk + gc + 4];
                af[mt][3] = As[(row + gm + 8) * LDS_ + kk + gc + 4];
            }
            uint32_t bf[8][2];
#pragma unroll
            for (int nt = 0; nt < 8; nt++) {
                const int col = wn + nt * 8;
                bf[nt][0] = Ws[(col + gm) * LDS_ + kk + gc];
                bf[nt][1] = Ws[(col + gm) * LDS_ + kk + gc + 4];
            }
#pragma unroll
            for (int mt = 0; mt < 2; mt++)
#pragma unroll
                for (int nt = 0; nt < 8; nt++)
                    mma_tf32(acc[mt][nt], af[mt], bf[nt]);
        }
    }

#pragma unroll
    for (int mt = 0; mt < 2; mt++) {
        const int row0 = bm * 128 + wm + mt * 16 + gm;
#pragma unroll
        for (int nt = 0; nt < 8; nt++) {
            const int col = bn * 128 + wn + nt * 8 + 2 * gc;
            float2 lo, hi;
            lo.x = act_rt(acc[mt][nt][0], ACT); lo.y = act_rt(acc[mt][nt][1], ACT);
            hi.x = act_rt(acc[mt][nt][2], ACT); hi.y = act_rt(acc[mt][nt][3], ACT);
            *reinterpret_cast<float2*>(C + (size_t)row0 * Nc + col)       = lo;
            *reinterpret_cast<float2*>(C + (size_t)(row0 + 8) * Nc + col) = hi;
        }
    }
}

// ---------------- f projection + decay gate ---------------------------------
__global__ void fdecay_kernel(const float* __restrict__ x, const float* __restrict__ Wf,
                              const float* __restrict__ llb, float* __restrict__ fgout)
{
    const int row  = blockIdx.x;
    const int h    = threadIdx.x >> 5;
    const int lane = threadIdx.x & 31;
    const float* xr = x  + (size_t)row * E_;
    const float* wr = Wf + (size_t)h   * E_;
    float s = 0.f;
    for (int e = lane; e < E_; e += 32) s = fmaf(xr[e], wr[e], s);
#pragma unroll
    for (int m = 16; m; m >>= 1) s += __shfl_xor_sync(0xffffffffu, s, m);
    if (lane == 0) {
        const float lb  = __expf(llb[h]);
        const float fgv = lb + (1.f - lb) * (1.f / (1.f + __expf(-s)));
        const int b = row >> 12;
        const int n = row & (N_ - 1);
        fgout[((size_t)b * H_ + h) * N_ + n] = fgv;
    }
}

// ---------------- householder: q -= 2*(q.beta)/(beta.beta+eps) * beta -------
__global__ void householder_kernel(float* __restrict__ q, const float* __restrict__ beta)
{
    const int row = blockIdx.x, t = threadIdx.x;
    const size_t base = (size_t)row * E_ + t * 4;
    const float4 b4 = *reinterpret_cast<const float4*>(beta + base);
    float4 q4 = *reinterpret_cast<float4*>(q + base);
    float ss = b4.x * b4.x + b4.y * b4.y + b4.z * b4.z + b4.w * b4.w;
    float dq = q4.x * b4.x + q4.y * b4.y + q4.z * b4.z + q4.w * b4.w;
#pragma unroll
    for (int m = 16; m; m >>= 1) {
        ss += __shfl_xor_sync(0xffffffffu, ss, m);
        dq += __shfl_xor_sync(0xffffffffu, dq, m);
    }
    __shared__ float sred[2][8];
    const int w = t >> 5, lane = t & 31;
    if (lane == 0) { sred[0][w] = ss; sred[1][w] = dq; }
    __syncthreads();
    float sst = 0.f, dqt = 0.f;
#pragma unroll
    for (int i = 0; i < 8; i++) { sst += sred[0][i]; dqt += sred[1][i]; }
    const float coef = 2.f * dqt / (sst + 1e-12f);
    q4.x -= coef * b4.x; q4.y -= coef * b4.y;
    q4.z -= coef * b4.z; q4.w -= coef * b4.w;
    *reinterpret_cast<float4*>(q + base) = q4;
}

// ---------------- GLA recurrence --------------------------------------------
// 16 v-splits per (b,h): grid 256 blocks. 128 thr: 8 cols x 16 thr, S[8]/thr.
__global__ void __launch_bounds__(128) gla_kernel(
    const float* __restrict__ q, const float* __restrict__ k,
    const float* __restrict__ v, const float* __restrict__ fg,
    float* __restrict__ o)
{
    const int bid = blockIdx.x;
    const int vg  = bid & 15;           // 16 v-splits of 8 cols
    const int bh  = bid >> 4;
    const int b   = bh >> 3, h = bh & 7;
    const int t   = threadIdx.x;
    const int col = t >> 4, kg = t & 15;

    __shared__ alignas(16) float sk[2][128];
    __shared__ alignas(16) float sq[2][128];
    __shared__ float sv[2][8];
    __shared__ float sg[2];

    const size_t rowbase = (size_t)b * N_ * E_ + (size_t)h * R_;
    const float* kb  = k + rowbase;
    const float* qb  = q + rowbase;
    const float* vb  = v + rowbase + vg * 8;
    const float* fgb = fg + (size_t)bh * N_;
    float* ob = o + rowbase + vg * 8 + col;

    float S[8];
#pragma unroll
    for (int i = 0; i < 8; i++) S[i] = 0.f;

    sk[0][t] = kb[t];
    sq[0][t] = qb[t];
    if (t < 8) sv[0][t] = vb[t];
    if (t == 0) sg[0] = fgb[0];
    __syncthreads();

    const float scale = rsqrtf((float)R_);
    for (int n = 0; n < N_; n++) {
        const int cur = n & 1, nxt = cur ^ 1;
        if (n + 1 < N_) {
            const size_t off = (size_t)(n + 1) * E_;
            sk[nxt][t] = kb[off + t];
            sq[nxt][t] = qb[off + t];
            if (t < 8) sv[nxt][t] = vb[off + t];
            if (t == 0) sg[nxt] = fgb[n + 1];
        }
        const float eg   = sg[cur];
        const float vval = sv[cur][col];
        const float4 k4a = *reinterpret_cast<const float4*>(&sk[cur][kg * 4]);
        const float4 q4a = *reinterpret_cast<const float4*>(&sq[cur][kg * 4]);
        const float4 k4b = *reinterpret_cast<const float4*>(&sk[cur][kg * 4 + 64]);
        const float4 q4b = *reinterpret_cast<const float4*>(&sq[cur][kg * 4 + 64]);
        float a0 = 0.f, a1 = 0.f;
        S[0] = fmaf(S[0], eg, k4a.x * vval); a0 = fmaf(q4a.x, S[0], a0);
        S[1] = fmaf(S[1], eg, k4a.y * vval); a0 = fmaf(q4a.y, S[1], a0);
        S[2] = fmaf(S[2], eg, k4a.z * vval); a0 = fmaf(q4a.z, S[2], a0);
        S[3] = fmaf(S[3], eg, k4a.w * vval); a0 = fmaf(q4a.w, S[3], a0);
        S[4] = fmaf(S[4], eg, k4b.x * vval); a1 = fmaf(q4b.x, S[4], a1);
        S[5] = fmaf(S[5], eg, k4b.y * vval); a1 = fmaf(q4b.y, S[5], a1);
        S[6] = fmaf(S[6], eg, k4b.z * vval); a1 = fmaf(q4b.z, S[6], a1);
        S[7] = fmaf(S[7], eg, k4b.w * vval); a1 = fmaf(q4b.w, S[7], a1);
        float acc = a0 + a1;
        acc += __shfl_xor_sync(0xffffffffu, acc, 1);
        acc += __shfl_xor_sync(0xffffffffu, acc, 2);
        acc += __shfl_xor_sync(0xffffffffu, acc, 4);
        acc += __shfl_xor_sync(0xffffffffu, acc, 8);
        if (kg == 0) ob[(size_t)n * E_] = acc * scale;
        __syncthreads();
    }
}

// ---------------- gate * o, then LayerNorm (weight only) --------------------
__global__ void gateln_kernel(const float* __restrict__ o, const float* __restrict__ gate,
                              const float* __restrict__ gamma, float* __restrict__ out)
{
    const int row = blockIdx.x, t = threadIdx.x;
    const size_t base = (size_t)row * E_ + t * 4;
    float4 ov = *reinterpret_cast<const float4*>(o + base);
    const float4 gv = *reinterpret_cast<const float4*>(gate + base);
    ov.x *= gv.x; ov.y *= gv.y; ov.z *= gv.z; ov.w *= gv.w;
    float s  = ov.x + ov.y + ov.z + ov.w;
    float s2 = ov.x * ov.x + ov.y * ov.y + ov.z * ov.z + ov.w * ov.w;
#pragma unroll
    for (int m = 16; m; m >>= 1) {
        s  += __shfl_xor_sync(0xffffffffu, s,  m);
        s2 += __shfl_xor_sync(0xffffffffu, s2, m);
    }
    __shared__ float sred[2][8];
    const int w = t >> 5, lane = t & 31;
    if (lane == 0) { sred[0][w] = s; sred[1][w] = s2; }
    __syncthreads();
    float st = 0.f, s2t = 0.f;
#pragma unroll
    for (int i = 0; i < 8; i++) { st += sred[0][i]; s2t += sred[1][i]; }
    const float mu  = st * (1.f / E_);
    const float var = s2t * (1.f / E_) - mu * mu;
    const float r   = rsqrtf(var + 1e-5f);
    const float4 gm = *reinterpret_cast<const float4*>(gamma + t * 4);
    float4 res;
    res.x = (ov.x - mu) * r * gm.x;
    res.y = (ov.y - mu) * r * gm.y;
    res.z = (ov.z - mu) * r * gm.z;
    res.w = (ov.w - mu) * r * gm.w;
    *reinterpret_cast<float4*>(out + base) = res;
}

// ---------------- launch ----------------------------------------------------
extern "C" void kernel_launch(void* const* d_in, const int* in_sizes, int n_in,
                              void* d_out, int out_size)
{
    (void)in_sizes; (void)n_in; (void)out_size;
    const float* x   = (const float*)d_in[0];
    const float* llb = (const float*)d_in[1];
    const float* Wq  = (const float*)d_in[2];
    const float* Wk  = (const float*)d_in[3];
    const float* Wv  = (const float*)d_in[4];
    const float* Wf  = (const float*)d_in[5];
    const float* Wb1 = (const float*)d_in[6];
    const float* Wb2 = (const float*)d_in[7];
    const float* Wg1 = (const float*)d_in[8];
    const float* Wg2 = (const float*)d_in[9];
    const float* gamma = (const float*)d_in[10];
    const float* Wo  = (const float*)d_in[11];
    float* out = (float*)d_out;

    float *q, *k, *v, *beta, *gate, *o, *t2, *u, *u2, *fg;
    cudaGetSymbolAddress((void**)&q,    g_q);
    cudaGetSymbolAddress((void**)&k,    g_k);
    cudaGetSymbolAddress((void**)&v,    g_v);
    cudaGetSymbolAddress((void**)&beta, g_beta);
    cudaGetSymbolAddress((void**)&gate, g_gate);
    cudaGetSymbolAddress((void**)&o,    g_o);
    cudaGetSymbolAddress((void**)&t2,   g_t2);
    cudaGetSymbolAddress((void**)&u,    g_u);
    cudaGetSymbolAddress((void**)&u2,   g_u2);
    cudaGetSymbolAddress((void**)&fg,   g_fg);

    const dim3 blk(256);

    // low-rank projections: u = x Wb1^T, u2 = x Wg1^T (fused, z=2)
    {
        GemmBatch gb{};
        gb.A[0] = x;   gb.W[0] = Wb1; gb.C[0] = u;  gb.act[0] = 0;
        gb.A[1] = x;   gb.W[1] = Wg1; gb.C[1] = u2; gb.act[1] = 0;
        gemm_tf32<<<dim3(R_/128, ROWS_/128, 2), blk>>>(gb, ROWS_, R_, E_);
    }
    // qkv projections (fused, z=3)
    {
        GemmBatch gb{};
        gb.A[0] = x; gb.W[0] = Wq; gb.C[0] = q; gb.act[0] = 1;
        gb.A[1] = x; gb.W[1] = Wk; gb.C[1] = k; gb.act[1] = 1;
        gb.A[2] = x; gb.W[2] = Wv; gb.C[2] = v; gb.act[2] = 0;
        gemm_tf32<<<dim3(E_/128, ROWS_/128, 3), blk>>>(gb, ROWS_, E_, E_);
    }
    fdecay_kernel<<<ROWS_, 256>>>(x, Wf, llb, fg);

    // beta = silu(u Wb2^T), gate = sigmoid(u2 Wg2^T) (fused, z=2)
    {
        GemmBatch gb{};
        gb.A[0] = u;  gb.W[0] = Wb2; gb.C[0] = beta; gb.act[0] = 1;
        gb.A[1] = u2; gb.W[1] = Wg2; gb.C[1] = gate; gb.act[1] = 2;
        gemm_tf32<<<dim3(E_/128, ROWS_/128, 2), blk>>>(gb, ROWS_, E_, R_);
    }

    householder_kernel<<<ROWS_, 256>>>(q, beta);

    gla_kernel<<<B_ * H_ * 16, 128>>>(q, k, v, fg, o);

    gateln_kernel<<<ROWS_, 256>>>(o, gate, gamma, t2);

    // output projection
    {
        GemmBatch gb{};
        gb.A[0] = t2; gb.W[0] = Wo; gb.C[0] = out; gb.act[0] = 0;
        gemm_tf32<<<dim3(E_/128, ROWS_/128, 1), blk>>>(gb, ROWS_, E_, E_);
    }
}

// round 4
// speedup vs baseline: 3.4781x; 2.4477x over previous
#include <cuda_runtime.h>
#include <math.h>
#include <stdint.h>

#define B_ 2
#define N_ 4096
#define E_ 1024
#define R_ 128
#define H_ 8
#define ROWS_ (B_*N_)   // 8192
#define CH_ 16          // GLA staging depth (steps per smem stage)

// ---------------- scratch (static device allocations; no cudaMalloc) -------
__device__ float g_q   [ROWS_*E_];
__device__ float g_k   [ROWS_*E_];
__device__ float g_v   [ROWS_*E_];
__device__ float g_beta[ROWS_*E_];
__device__ float g_gate[ROWS_*E_];
__device__ float g_o   [ROWS_*E_];
__device__ float g_t2  [ROWS_*E_];
__device__ float g_u   [ROWS_*R_];
__device__ float g_u2  [ROWS_*R_];
__device__ float g_fg  [B_*H_*N_];

// ---------------- helpers ----------------------------------------------------
__device__ __forceinline__ float act_rt(float x, int a) {
    if (a == 1) return x * (1.f / (1.f + __expf(-x)));   // silu
    if (a == 2) return 1.f / (1.f + __expf(-x));          // sigmoid
    return x;
}

__device__ __forceinline__ uint32_t f2tf32(float x) {
    uint32_t r;
    asm("cvt.rna.tf32.f32 %0, %1;" : "=r"(r) : "f"(x));
    return r;
}

__device__ __forceinline__ void mma_tf32(float c[4], const uint32_t a[4], const uint32_t b[2]) {
    asm volatile(
        "mma.sync.aligned.m16n8k8.row.col.f32.tf32.tf32.f32 "
        "{%0,%1,%2,%3}, {%4,%5,%6,%7}, {%8,%9}, {%0,%1,%2,%3};"
        : "+f"(c[0]), "+f"(c[1]), "+f"(c[2]), "+f"(c[3])
        : "r"(a[0]), "r"(a[1]), "r"(a[2]), "r"(a[3]), "r"(b[0]), "r"(b[1]));
}

__device__ __forceinline__ void cp16(void* smem, const void* gmem) {
    uint32_t s = (uint32_t)__cvta_generic_to_shared(smem);
    asm volatile("cp.async.cg.shared.global [%0], [%1], 16;" :: "r"(s), "l"(gmem));
}

struct GemmBatch {
    const float* A[3];
    const float* W[3];
    float*       C[3];
    int          act[3];
};

// ---------------- tf32 tensor-core NT GEMM (pipelined, batched via z) -------
#define LDS_ 36
__global__ void __launch_bounds__(256, 2) gemm_tf32(GemmBatch gb, int M, int Nc, int K)
{
    __shared__ uint32_t As[128 * LDS_];
    __shared__ uint32_t Ws[128 * LDS_];
    const int z = blockIdx.z;
    const float* __restrict__ A = gb.A[z];
    const float* __restrict__ W = gb.W[z];
    float* __restrict__ C = gb.C[z];
    const int ACT = gb.act[z];

    const int t    = threadIdx.x;
    const int warp = t >> 5, lane = t & 31;
    const int bm = blockIdx.y, bn = blockIdx.x;
    const int wm = (warp >> 1) * 32;
    const int wn = (warp & 1) * 64;
    const int gm = lane >> 2, gc = lane & 3;

    float acc[2][8][4];
#pragma unroll
    for (int i = 0; i < 2; i++)
#pragma unroll
        for (int j = 0; j < 8; j++)
#pragma unroll
            for (int l = 0; l < 4; l++) acc[i][j][l] = 0.f;

    const int ldr = t >> 1;
    const int ldc = (t & 1) * 16;
    const float* Ap = A + (size_t)(bm * 128 + ldr) * K + ldc;
    const float* Wp = W + (size_t)(bn * 128 + ldr) * K + ldc;

    float4 a4[4], w4[4];
#pragma unroll
    for (int i = 0; i < 4; i++) {
        a4[i] = *reinterpret_cast<const float4*>(Ap + i * 4);
        w4[i] = *reinterpret_cast<const float4*>(Wp + i * 4);
    }

    for (int kt = 0; kt < K; kt += 32) {
        __syncthreads();
#pragma unroll
        for (int i = 0; i < 4; i++) {
            uint4 av, wv;
            av.x = f2tf32(a4[i].x); av.y = f2tf32(a4[i].y);
            av.z = f2tf32(a4[i].z); av.w = f2tf32(a4[i].w);
            wv.x = f2tf32(w4[i].x); wv.y = f2tf32(w4[i].y);
            wv.z = f2tf32(w4[i].z); wv.w = f2tf32(w4[i].w);
            *reinterpret_cast<uint4*>(&As[ldr * LDS_ + ldc + i * 4]) = av;
            *reinterpret_cast<uint4*>(&Ws[ldr * LDS_ + ldc + i * 4]) = wv;
        }
        __syncthreads();
        if (kt + 32 < K) {
#pragma unroll
            for (int i = 0; i < 4; i++) {
                a4[i] = *reinterpret_cast<const float4*>(Ap + kt + 32 + i * 4);
                w4[i] = *reinterpret_cast<const float4*>(Wp + kt + 32 + i * 4);
            }
        }
#pragma unroll
        for (int kk = 0; kk < 32; kk += 8) {
            uint32_t af[2][4];
#pragma unroll
            for (int mt = 0; mt < 2; mt++) {
                const int row = wm + mt * 16;
                af[mt][0] = As[(row + gm)     * LDS_ + kk + gc];
                af[mt][1] = As[(row + gm + 8) * LDS_ + kk + gc];
                af[mt][2] = As[(row + gm)     * LDS_ + kk + gc + 4];
                af[mt][3] = As[(row + gm + 8) * LDS_ + kk + gc + 4];
            }
            uint32_t bf[8][2];
#pragma unroll
            for (int nt = 0; nt < 8; nt++) {
                const int col = wn + nt * 8;
                bf[nt][0] = Ws[(col + gm) * LDS_ + kk + gc];
                bf[nt][1] = Ws[(col + gm) * LDS_ + kk + gc + 4];
            }
#pragma unroll
            for (int mt = 0; mt < 2; mt++)
#pragma unroll
                for (int nt = 0; nt < 8; nt++)
                    mma_tf32(acc[mt][nt], af[mt], bf[nt]);
        }
    }

#pragma unroll
    for (int mt = 0; mt < 2; mt++) {
        const int row0 = bm * 128 + wm + mt * 16 + gm;
#pragma unroll
        for (int nt = 0; nt < 8; nt++) {
            const int col = bn * 128 + wn + nt * 8 + 2 * gc;
            float2 lo, hi;
            lo.x = act_rt(acc[mt][nt][0], ACT); lo.y = act_rt(acc[mt][nt][1], ACT);
            hi.x = act_rt(acc[mt][nt][2], ACT); hi.y = act_rt(acc[mt][nt][3], ACT);
            *reinterpret_cast<float2*>(C + (size_t)row0 * Nc + col)       = lo;
            *reinterpret_cast<float2*>(C + (size_t)(row0 + 8) * Nc + col) = hi;
        }
    }
}

// ---------------- f projection + decay gate ---------------------------------
__global__ void fdecay_kernel(const float* __restrict__ x, const float* __restrict__ Wf,
                              const float* __restrict__ llb, float* __restrict__ fgout)
{
    const int row  = blockIdx.x;
    const int h    = threadIdx.x >> 5;
    const int lane = threadIdx.x & 31;
    const float* xr = x  + (size_t)row * E_;
    const float* wr = Wf + (size_t)h   * E_;
    float s = 0.f;
    for (int e = lane; e < E_; e += 32) s = fmaf(xr[e], wr[e], s);
#pragma unroll
    for (int m = 16; m; m >>= 1) s += __shfl_xor_sync(0xffffffffu, s, m);
    if (lane == 0) {
        const float lb  = __expf(llb[h]);
        const float fgv = lb + (1.f - lb) * (1.f / (1.f + __expf(-s)));
        const int b = row >> 12;
        const int n = row & (N_ - 1);
        fgout[((size_t)b * H_ + h) * N_ + n] = fgv;
    }
}

// ---------------- householder: q -= 2*(q.beta)/(beta.beta+eps) * beta -------
__global__ void householder_kernel(float* __restrict__ q, const float* __restrict__ beta)
{
    const int row = blockIdx.x, t = threadIdx.x;
    const size_t base = (size_t)row * E_ + t * 4;
    const float4 b4 = *reinterpret_cast<const float4*>(beta + base);
    float4 q4 = *reinterpret_cast<float4*>(q + base);
    float ss = b4.x * b4.x + b4.y * b4.y + b4.z * b4.z + b4.w * b4.w;
    float dq = q4.x * b4.x + q4.y * b4.y + q4.z * b4.z + q4.w * b4.w;
#pragma unroll
    for (int m = 16; m; m >>= 1) {
        ss += __shfl_xor_sync(0xffffffffu, ss, m);
        dq += __shfl_xor_sync(0xffffffffu, dq, m);
    }
    __shared__ float sred[2][8];
    const int w = t >> 5, lane = t & 31;
    if (lane == 0) { sred[0][w] = ss; sred[1][w] = dq; }
    __syncthreads();
    float sst = 0.f, dqt = 0.f;
#pragma unroll
    for (int i = 0; i < 8; i++) { sst += sred[0][i]; dqt += sred[1][i]; }
    const float coef = 2.f * dqt / (sst + 1e-12f);
    q4.x -= coef * b4.x; q4.y -= coef * b4.y;
    q4.z -= coef * b4.z; q4.w -= coef * b4.w;
    *reinterpret_cast<float4*>(q + base) = q4;
}

// ---------------- GLA recurrence (cp.async 16-step staged) ------------------
// block = (b, h, vg∈0..15): 8 v-cols. 128 thr: col = t>>4, kg = t&15 (8 kk each).
__global__ void __launch_bounds__(128) gla_kernel(
    const float* __restrict__ q, const float* __restrict__ k,
    const float* __restrict__ v, const float* __restrict__ fg,
    float* __restrict__ o)
{
    const int bid = blockIdx.x;
    const int vg  = bid & 15;
    const int bh  = bid >> 4;
    const int b   = bh >> 3, h = bh & 7;
    const int t   = threadIdx.x;
    const int col = t >> 4, kg = t & 15;

    __shared__ alignas(16) float sk[2][CH_][128];
    __shared__ alignas(16) float sq[2][CH_][128];
    __shared__ alignas(16) float sv[2][CH_][8];
    __shared__ alignas(16) float sg[2][CH_];

    const size_t rowbase = (size_t)b * N_ * E_ + (size_t)h * R_;
    const float* kb  = k + rowbase;
    const float* qb  = q + rowbase;
    const float* vb  = v + rowbase + vg * 8;
    const float* fgb = fg + (size_t)bh * N_;
    float* ob = o + rowbase + vg * 8 + col;

    // stage loader: 16 steps of k (2KB), q (2KB), v (512B), fg (64B)
    auto issue_stage = [&](int st, int n0) {
#pragma unroll
        for (int c = 0; c < 8; c++) {
            const int idx  = c * 128 + t;          // 0..1023
            const int step = idx >> 5;              // 0..31? no: 1024/32 = 32.. careful
            // 16 steps * 32 float4 = 512 float4 per tensor; 128 thr * 4 chunks
            (void)step;
        }
        // k,q: 512 float4 each -> 4 chunks per thread per tensor
#pragma unroll
        for (int c = 0; c < 4; c++) {
            const int idx  = c * 128 + t;          // 0..511
            const int step = idx >> 5;              // 0..15
            const int part = idx & 31;              // float4 index within row
            cp16(&sk[st][step][part * 4], kb + (size_t)(n0 + step) * E_ + part * 4);
            cp16(&sq[st][step][part * 4], qb + (size_t)(n0 + step) * E_ + part * 4);
        }
        if (t < 32) {                               // v: 16 steps * 2 float4
            const int step = t >> 1, part = t & 1;
            cp16(&sv[st][step][part * 4], vb + (size_t)(n0 + step) * E_ + part * 4);
        }
        if (t < 4)                                  // fg: 16 floats
            cp16(&sg[st][t * 4], fgb + n0 + t * 4);
    };

    float S[8];
#pragma unroll
    for (int i = 0; i < 8; i++) S[i] = 0.f;

    issue_stage(0, 0);
    asm volatile("cp.async.commit_group;" ::: "memory");

    const float scale = rsqrtf((float)R_);
    for (int blk = 0; blk < N_ / CH_; blk++) {
        const int cur = blk & 1, nxt = cur ^ 1;
        if (blk + 1 < N_ / CH_) issue_stage(nxt, (blk + 1) * CH_);
        asm volatile("cp.async.commit_group;" ::: "memory");
        asm volatile("cp.async.wait_group 1;" ::: "memory");
        __syncthreads();
#pragma unroll 4
        for (int s = 0; s < CH_; s++) {
            const float eg   = sg[cur][s];
            const float vval = sv[cur][s][col];
            const float4 k4a = *reinterpret_cast<const float4*>(&sk[cur][s][kg * 8]);
            const float4 q4a = *reinterpret_cast<const float4*>(&sq[cur][s][kg * 8]);
            const float4 k4b = *reinterpret_cast<const float4*>(&sk[cur][s][kg * 8 + 4]);
            const float4 q4b = *reinterpret_cast<const float4*>(&sq[cur][s][kg * 8 + 4]);
            float a0 = 0.f, a1 = 0.f;
            S[0] = fmaf(S[0], eg, k4a.x * vval); a0 = fmaf(q4a.x, S[0], a0);
            S[1] = fmaf(S[1], eg, k4a.y * vval); a0 = fmaf(q4a.y, S[1], a0);
            S[2] = fmaf(S[2], eg, k4a.z * vval); a0 = fmaf(q4a.z, S[2], a0);
            S[3] = fmaf(S[3], eg, k4a.w * vval); a0 = fmaf(q4a.w, S[3], a0);
            S[4] = fmaf(S[4], eg, k4b.x * vval); a1 = fmaf(q4b.x, S[4], a1);
            S[5] = fmaf(S[5], eg, k4b.y * vval); a1 = fmaf(q4b.y, S[5], a1);
            S[6] = fmaf(S[6], eg, k4b.z * vval); a1 = fmaf(q4b.z, S[6], a1);
            S[7] = fmaf(S[7], eg, k4b.w * vval); a1 = fmaf(q4b.w, S[7], a1);
            float acc = a0 + a1;
            acc += __shfl_xor_sync(0xffffffffu, acc, 1);
            acc += __shfl_xor_sync(0xffffffffu, acc, 2);
            acc += __shfl_xor_sync(0xffffffffu, acc, 4);
            acc += __shfl_xor_sync(0xffffffffu, acc, 8);
            if (kg == 0) ob[(size_t)(blk * CH_ + s) * E_] = acc * scale;
        }
        __syncthreads();
    }
}

// ---------------- gate * o, then LayerNorm (weight only) --------------------
__global__ void gateln_kernel(const float* __restrict__ o, const float* __restrict__ gate,
                              const float* __restrict__ gamma, float* __restrict__ out)
{
    const int row = blockIdx.x, t = threadIdx.x;
    const size_t base = (size_t)row * E_ + t * 4;
    float4 ov = *reinterpret_cast<const float4*>(o + base);
    const float4 gv = *reinterpret_cast<const float4*>(gate + base);
    ov.x *= gv.x; ov.y *= gv.y; ov.z *= gv.z; ov.w *= gv.w;
    float s  = ov.x + ov.y + ov.z + ov.w;
    float s2 = ov.x * ov.x + ov.y * ov.y + ov.z * ov.z + ov.w * ov.w;
#pragma unroll
    for (int m = 16; m; m >>= 1) {
        s  += __shfl_xor_sync(0xffffffffu, s,  m);
        s2 += __shfl_xor_sync(0xffffffffu, s2, m);
    }
    __shared__ float sred[2][8];
    const int w = t >> 5, lane = t & 31;
    if (lane == 0) { sred[0][w] = s; sred[1][w] = s2; }
    __syncthreads();
    float st = 0.f, s2t = 0.f;
#pragma unroll
    for (int i = 0; i < 8; i++) { st += sred[0][i]; s2t += sred[1][i]; }
    const float mu  = st * (1.f / E_);
    const float var = s2t * (1.f / E_) - mu * mu;
    const float r   = rsqrtf(var + 1e-5f);
    const float4 gm = *reinterpret_cast<const float4*>(gamma + t * 4);
    float4 res;
    res.x = (ov.x - mu) * r * gm.x;
    res.y = (ov.y - mu) * r * gm.y;
    res.z = (ov.z - mu) * r * gm.z;
    res.w = (ov.w - mu) * r * gm.w;
    *reinterpret_cast<float4*>(out + base) = res;
}

// ---------------- launch ----------------------------------------------------
extern "C" void kernel_launch(void* const* d_in, const int* in_sizes, int n_in,
                              void* d_out, int out_size)
{
    (void)in_sizes; (void)n_in; (void)out_size;
    const float* x   = (const float*)d_in[0];
    const float* llb = (const float*)d_in[1];
    const float* Wq  = (const float*)d_in[2];
    const float* Wk  = (const float*)d_in[3];
    const float* Wv  = (const float*)d_in[4];
    const float* Wf  = (const float*)d_in[5];
    const float* Wb1 = (const float*)d_in[6];
    const float* Wb2 = (const float*)d_in[7];
    const float* Wg1 = (const float*)d_in[8];
    const float* Wg2 = (const float*)d_in[9];
    const float* gamma = (const float*)d_in[10];
    const float* Wo  = (const float*)d_in[11];
    float* out = (float*)d_out;

    float *q, *k, *v, *beta, *gate, *o, *t2, *u, *u2, *fg;
    cudaGetSymbolAddress((void**)&q,    g_q);
    cudaGetSymbolAddress((void**)&k,    g_k);
    cudaGetSymbolAddress((void**)&v,    g_v);
    cudaGetSymbolAddress((void**)&beta, g_beta);
    cudaGetSymbolAddress((void**)&gate, g_gate);
    cudaGetSymbolAddress((void**)&o,    g_o);
    cudaGetSymbolAddress((void**)&t2,   g_t2);
    cudaGetSymbolAddress((void**)&u,    g_u);
    cudaGetSymbolAddress((void**)&u2,   g_u2);
    cudaGetSymbolAddress((void**)&fg,   g_fg);

    const dim3 blk(256);

    // low-rank projections: u = x Wb1^T, u2 = x Wg1^T (fused, z=2)
    {
        GemmBatch gb{};
        gb.A[0] = x;   gb.W[0] = Wb1; gb.C[0] = u;  gb.act[0] = 0;
        gb.A[1] = x;   gb.W[1] = Wg1; gb.C[1] = u2; gb.act[1] = 0;
        gemm_tf32<<<dim3(R_/128, ROWS_/128, 2), blk>>>(gb, ROWS_, R_, E_);
    }
    // qkv projections (fused, z=3)
    {
        GemmBatch gb{};
        gb.A[0] = x; gb.W[0] = Wq; gb.C[0] = q; gb.act[0] = 1;
        gb.A[1] = x; gb.W[1] = Wk; gb.C[1] = k; gb.act[1] = 1;
        gb.A[2] = x; gb.W[2] = Wv; gb.C[2] = v; gb.act[2] = 0;
        gemm_tf32<<<dim3(E_/128, ROWS_/128, 3), blk>>>(gb, ROWS_, E_, E_);
    }
    fdecay_kernel<<<ROWS_, 256>>>(x, Wf, llb, fg);

    // beta = silu(u Wb2^T), gate = sigmoid(u2 Wg2^T) (fused, z=2)
    {
        GemmBatch gb{};
        gb.A[0] = u;  gb.W[0] = Wb2; gb.C[0] = beta; gb.act[0] = 1;
        gb.A[1] = u2; gb.W[1] = Wg2; gb.C[1] = gate; gb.act[1] = 2;
        gemm_tf32<<<dim3(E_/128, ROWS_/128, 2), blk>>>(gb, ROWS_, E_, R_);
    }

    householder_kernel<<<ROWS_, 256>>>(q, beta);

    gla_kernel<<<B_ * H_ * 16, 128>>>(q, k, v, fg, o);

    gateln_kernel<<<ROWS_, 256>>>(o, gate, gamma, t2);

    // output projection
    {
        GemmBatch gb{};
        gb.A[0] = t2; gb.W[0] = Wo; gb.C[0] = out; gb.act[0] = 0;
        gemm_tf32<<<dim3(E_/128, ROWS_/128, 1), blk>>>(gb, ROWS_, E_, E_);
    }
}

// round 5
// speedup vs baseline: 3.6236x; 1.0418x over previous
#include <cuda_runtime.h>
#include <math.h>
#include <stdint.h>

#define B_ 2
#define N_ 4096
#define E_ 1024
#define R_ 128
#define H_ 8
#define ROWS_ (B_*N_)   // 8192
#define CH_ 16          // GLA staging depth

// ---------------- scratch (static device allocations; no cudaMalloc) -------
__device__ float g_q   [ROWS_*E_];
__device__ float g_k   [ROWS_*E_];
__device__ float g_v   [ROWS_*E_];
__device__ float g_beta[ROWS_*E_];
__device__ float g_gate[ROWS_*E_];
__device__ float g_o   [ROWS_*E_];
__device__ float g_t2  [ROWS_*E_];
__device__ float g_u   [ROWS_*R_];
__device__ float g_u2  [ROWS_*R_];
__device__ float g_fg  [B_*H_*N_];

// ---------------- helpers ----------------------------------------------------
__device__ __forceinline__ float act_rt(float x, int a) {
    if (a == 1) return x * (1.f / (1.f + __expf(-x)));   // silu
    if (a == 2) return 1.f / (1.f + __expf(-x));          // sigmoid
    return x;
}

__device__ __forceinline__ uint32_t f2tf32(float x) {
    uint32_t r;
    asm("cvt.rna.tf32.f32 %0, %1;" : "=r"(r) : "f"(x));
    return r;
}

__device__ __forceinline__ void mma_tf32(float c[4], const uint32_t a[4], const uint32_t b[2]) {
    asm volatile(
        "mma.sync.aligned.m16n8k8.row.col.f32.tf32.tf32.f32 "
        "{%0,%1,%2,%3}, {%4,%5,%6,%7}, {%8,%9}, {%0,%1,%2,%3};"
        : "+f"(c[0]), "+f"(c[1]), "+f"(c[2]), "+f"(c[3])
        : "r"(a[0]), "r"(a[1]), "r"(a[2]), "r"(a[3]), "r"(b[0]), "r"(b[1]));
}

__device__ __forceinline__ void ldsm4(uint32_t& r0, uint32_t& r1, uint32_t& r2, uint32_t& r3,
                                      uint32_t saddr) {
    asm volatile("ldmatrix.sync.aligned.m8n8.x4.shared.b16 {%0,%1,%2,%3}, [%4];"
        : "=r"(r0), "=r"(r1), "=r"(r2), "=r"(r3) : "r"(saddr));
}

__device__ __forceinline__ void cp16(void* smem, const void* gmem) {
    uint32_t s = (uint32_t)__cvta_generic_to_shared(smem);
    asm volatile("cp.async.cg.shared.global [%0], [%1], 16;" :: "r"(s), "l"(gmem));
}

struct GemmBatch {
    const float* A[3];
    const float* W[3];
    float*       C[3];
    int          act[3];
};

// ---------------- tf32 tensor-core NT GEMM ----------------------------------
// C[m,n] = act(sum_k A[m,k]*W[n,k]); M,Nc mult of 128; K mult of 32.
// 256 thr = 8 warps (4m x 2n); warp tile 32x64; K-chunk 32.
// Double-buffered smem (1 bar/chunk) + ldmatrix fragments.
#define LDSW 36
#define BUFU (128 * LDSW)          // uint32s per tensor per buffer
__global__ void __launch_bounds__(256, 2) gemm_tf32(GemmBatch gb, int M, int Nc, int K)
{
    extern __shared__ uint32_t sdyn[];   // [2][2][128][LDSW] : As then Ws
    uint32_t* As = sdyn;                 // As[buf] = sdyn + buf*BUFU
    uint32_t* Ws = sdyn + 2 * BUFU;

    const int z = blockIdx.z;
    const float* __restrict__ A = gb.A[z];
    const float* __restrict__ W = gb.W[z];
    float* __restrict__ C = gb.C[z];
    const int ACT = gb.act[z];

    const int t    = threadIdx.x;
    const int warp = t >> 5, lane = t & 31;
    const int bm = blockIdx.y, bn = blockIdx.x;
    const int wm = (warp >> 1) * 32;
    const int wn = (warp & 1) * 64;
    const int gm = lane >> 2, gc = lane & 3;

    float acc[2][8][4];
#pragma unroll
    for (int i = 0; i < 2; i++)
#pragma unroll
        for (int j = 0; j < 8; j++)
#pragma unroll
            for (int l = 0; l < 4; l++) acc[i][j][l] = 0.f;

    const int ldr = t >> 1;
    const int ldc = (t & 1) * 16;
    const float* Ap = A + (size_t)(bm * 128 + ldr) * K + ldc;
    const float* Wp = W + (size_t)(bn * 128 + ldr) * K + ldc;

    // ldmatrix lane-address components (byte offsets added later)
    const uint32_t aBase = (uint32_t)__cvta_generic_to_shared(As);
    const uint32_t wBase = (uint32_t)__cvta_generic_to_shared(Ws);
    // A: row = wm + mt*16 + ((lane>>3)&1)*8 + (lane&7); col = (lane>>4)*4 + kk
    const int aRow = wm + ((lane >> 3) & 1) * 8 + (lane & 7);
    const int aCol = (lane >> 4) * 4;
    // B: row = wn + p*16 + (lane>>4)*8 + (lane&7); col = ((lane>>3)&1)*4 + kk
    const int bRow = wn + (lane >> 4) * 8 + (lane & 7);
    const int bCol = ((lane >> 3) & 1) * 4;

    float4 a4[4], w4[4];
#pragma unroll
    for (int i = 0; i < 4; i++) {              // prologue loads (chunk 0)
        a4[i] = *reinterpret_cast<const float4*>(Ap + i * 4);
        w4[i] = *reinterpret_cast<const float4*>(Wp + i * 4);
    }

    int buf = 0;
    for (int kt = 0; kt < K; kt += 32, buf ^= 1) {
        // store staged chunk into buf (other buffer than the one being read)
        uint32_t* Ab = As + buf * BUFU;
        uint32_t* Wb = Ws + buf * BUFU;
#pragma unroll
        for (int i = 0; i < 4; i++) {
            uint4 av, wv;
            av.x = f2tf32(a4[i].x); av.y = f2tf32(a4[i].y);
            av.z = f2tf32(a4[i].z); av.w = f2tf32(a4[i].w);
            wv.x = f2tf32(w4[i].x); wv.y = f2tf32(w4[i].y);
            wv.z = f2tf32(w4[i].z); wv.w = f2tf32(w4[i].w);
            *reinterpret_cast<uint4*>(&Ab[ldr * LDSW + ldc + i * 4]) = av;
            *reinterpret_cast<uint4*>(&Wb[ldr * LDSW + ldc + i * 4]) = wv;
        }
        if (kt + 32 < K) {                      // prefetch next chunk
#pragma unroll
            for (int i = 0; i < 4; i++) {
                a4[i] = *reinterpret_cast<const float4*>(Ap + kt + 32 + i * 4);
                w4[i] = *reinterpret_cast<const float4*>(Wp + kt + 32 + i * 4);
            }
        }
        __syncthreads();                        // buf ready for all warps

        const uint32_t aB = aBase + (uint32_t)(buf * BUFU + aRow * LDSW + aCol) * 4u;
        const uint32_t wB = wBase + (uint32_t)(buf * BUFU + bRow * LDSW + bCol) * 4u;
#pragma unroll
        for (int kk = 0; kk < 32; kk += 8) {
            uint32_t af[2][4];
#pragma unroll
            for (int mt = 0; mt < 2; mt++)
                ldsm4(af[mt][0], af[mt][1], af[mt][2], af[mt][3],
                      aB + (uint32_t)(mt * 16 * LDSW + kk) * 4u);
            uint32_t bf[8][2];
#pragma unroll
            for (int p = 0; p < 4; p++) {
                uint32_t r0, r1, r2, r3;
                ldsm4(r0, r1, r2, r3, wB + (uint32_t)(p * 16 * LDSW + kk) * 4u);
                bf[2*p][0] = r0; bf[2*p][1] = r1;
                bf[2*p+1][0] = r2; bf[2*p+1][1] = r3;
            }
#pragma unroll
            for (int mt = 0; mt < 2; mt++)
#pragma unroll
                for (int nt = 0; nt < 8; nt++)
                    mma_tf32(acc[mt][nt], af[mt], bf[nt]);
        }
    }

#pragma unroll
    for (int mt = 0; mt < 2; mt++) {
        const int row0 = bm * 128 + wm + mt * 16 + gm;
#pragma unroll
        for (int nt = 0; nt < 8; nt++) {
            const int col = bn * 128 + wn + nt * 8 + 2 * gc;
            float2 lo, hi;
            lo.x = act_rt(acc[mt][nt][0], ACT); lo.y = act_rt(acc[mt][nt][1], ACT);
            hi.x = act_rt(acc[mt][nt][2], ACT); hi.y = act_rt(acc[mt][nt][3], ACT);
            *reinterpret_cast<float2*>(C + (size_t)row0 * Nc + col)       = lo;
            *reinterpret_cast<float2*>(C + (size_t)(row0 + 8) * Nc + col) = hi;
        }
    }
}
#define GEMM_SMEM (4 * BUFU * 4)   // bytes: 2 tensors x 2 buffers

// ---------------- f projection + decay gate ---------------------------------
__global__ void fdecay_kernel(const float* __restrict__ x, const float* __restrict__ Wf,
                              const float* __restrict__ llb, float* __restrict__ fgout)
{
    const int row  = blockIdx.x;
    const int h    = threadIdx.x >> 5;
    const int lane = threadIdx.x & 31;
    const float* xr = x  + (size_t)row * E_;
    const float* wr = Wf + (size_t)h   * E_;
    float s = 0.f;
    for (int e = lane; e < E_; e += 32) s = fmaf(xr[e], wr[e], s);
#pragma unroll
    for (int m = 16; m; m >>= 1) s += __shfl_xor_sync(0xffffffffu, s, m);
    if (lane == 0) {
        const float lb  = __expf(llb[h]);
        const float fgv = lb + (1.f - lb) * (1.f / (1.f + __expf(-s)));
        const int b = row >> 12;
        const int n = row & (N_ - 1);
        fgout[((size_t)b * H_ + h) * N_ + n] = fgv;
    }
}

// ---------------- householder: q -= 2*(q.beta)/(beta.beta+eps) * beta -------
__global__ void householder_kernel(float* __restrict__ q, const float* __restrict__ beta)
{
    const int row = blockIdx.x, t = threadIdx.x;
    const size_t base = (size_t)row * E_ + t * 4;
    const float4 b4 = *reinterpret_cast<const float4*>(beta + base);
    float4 q4 = *reinterpret_cast<float4*>(q + base);
    float ss = b4.x * b4.x + b4.y * b4.y + b4.z * b4.z + b4.w * b4.w;
    float dq = q4.x * b4.x + q4.y * b4.y + q4.z * b4.z + q4.w * b4.w;
#pragma unroll
    for (int m = 16; m; m >>= 1) {
        ss += __shfl_xor_sync(0xffffffffu, ss, m);
        dq += __shfl_xor_sync(0xffffffffu, dq, m);
    }
    __shared__ float sred[2][8];
    const int w = t >> 5, lane = t & 31;
    if (lane == 0) { sred[0][w] = ss; sred[1][w] = dq; }
    __syncthreads();
    float sst = 0.f, dqt = 0.f;
#pragma unroll
    for (int i = 0; i < 8; i++) { sst += sred[0][i]; dqt += sred[1][i]; }
    const float coef = 2.f * dqt / (sst + 1e-12f);
    q4.x -= coef * b4.x; q4.y -= coef * b4.y;
    q4.z -= coef * b4.z; q4.w -= coef * b4.w;
    *reinterpret_cast<float4*>(q + base) = q4;
}

// ---------------- GLA recurrence (cp.async 16-step staged) ------------------
__global__ void __launch_bounds__(128) gla_kernel(
    const float* __restrict__ q, const float* __restrict__ k,
    const float* __restrict__ v, const float* __restrict__ fg,
    float* __restrict__ o)
{
    const int bid = blockIdx.x;
    const int vg  = bid & 15;
    const int bh  = bid >> 4;
    const int b   = bh >> 3, h = bh & 7;
    const int t   = threadIdx.x;
    const int col = t >> 4, kg = t & 15;

    __shared__ alignas(16) float sk[2][CH_][128];
    __shared__ alignas(16) float sq[2][CH_][128];
    __shared__ alignas(16) float sv[2][CH_][8];
    __shared__ alignas(16) float sg[2][CH_];

    const size_t rowbase = (size_t)b * N_ * E_ + (size_t)h * R_;
    const float* kb  = k + rowbase;
    const float* qb  = q + rowbase;
    const float* vb  = v + rowbase + vg * 8;
    const float* fgb = fg + (size_t)bh * N_;
    float* ob = o + rowbase + vg * 8 + col;

    auto issue_stage = [&](int st, int n0) {
#pragma unroll
        for (int c = 0; c < 4; c++) {
            const int idx  = c * 128 + t;
            const int step = idx >> 5;
            const int part = idx & 31;
            cp16(&sk[st][step][part * 4], kb + (size_t)(n0 + step) * E_ + part * 4);
            cp16(&sq[st][step][part * 4], qb + (size_t)(n0 + step) * E_ + part * 4);
        }
        if (t < 32) {
            const int step = t >> 1, part = t & 1;
            cp16(&sv[st][step][part * 4], vb + (size_t)(n0 + step) * E_ + part * 4);
        }
        if (t < 4)
            cp16(&sg[st][t * 4], fgb + n0 + t * 4);
    };

    float S[8];
#pragma unroll
    for (int i = 0; i < 8; i++) S[i] = 0.f;

    issue_stage(0, 0);
    asm volatile("cp.async.commit_group;" ::: "memory");

    const float scale = rsqrtf((float)R_);
    for (int blk = 0; blk < N_ / CH_; blk++) {
        const int cur = blk & 1, nxt = cur ^ 1;
        if (blk + 1 < N_ / CH_) issue_stage(nxt, (blk + 1) * CH_);
        asm volatile("cp.async.commit_group;" ::: "memory");
        asm volatile("cp.async.wait_group 1;" ::: "memory");
        __syncthreads();
#pragma unroll 4
        for (int s = 0; s < CH_; s++) {
            const float eg   = sg[cur][s];
            const float vval = sv[cur][s][col];
            const float4 k4a = *reinterpret_cast<const float4*>(&sk[cur][s][kg * 8]);
            const float4 q4a = *reinterpret_cast<const float4*>(&sq[cur][s][kg * 8]);
            const float4 k4b = *reinterpret_cast<const float4*>(&sk[cur][s][kg * 8 + 4]);
            const float4 q4b = *reinterpret_cast<const float4*>(&sq[cur][s][kg * 8 + 4]);
            float a0 = 0.f, a1 = 0.f;
            S[0] = fmaf(S[0], eg, k4a.x * vval); a0 = fmaf(q4a.x, S[0], a0);
            S[1] = fmaf(S[1], eg, k4a.y * vval); a0 = fmaf(q4a.y, S[1], a0);
            S[2] = fmaf(S[2], eg, k4a.z * vval); a0 = fmaf(q4a.z, S[2], a0);
            S[3] = fmaf(S[3], eg, k4a.w * vval); a0 = fmaf(q4a.w, S[3], a0);
            S[4] = fmaf(S[4], eg, k4b.x * vval); a1 = fmaf(q4b.x, S[4], a1);
            S[5] = fmaf(S[5], eg, k4b.y * vval); a1 = fmaf(q4b.y, S[5], a1);
            S[6] = fmaf(S[6], eg, k4b.z * vval); a1 = fmaf(q4b.z, S[6], a1);
            S[7] = fmaf(S[7], eg, k4b.w * vval); a1 = fmaf(q4b.w, S[7], a1);
            float acc = a0 + a1;
            acc += __shfl_xor_sync(0xffffffffu, acc, 1);
            acc += __shfl_xor_sync(0xffffffffu, acc, 2);
            acc += __shfl_xor_sync(0xffffffffu, acc, 4);
            acc += __shfl_xor_sync(0xffffffffu, acc, 8);
            if (kg == 0) ob[(size_t)(blk * CH_ + s) * E_] = acc * scale;
        }
        __syncthreads();
    }
}

// ---------------- gate * o, then LayerNorm (weight only) --------------------
__global__ void gateln_kernel(const float* __restrict__ o, const float* __restrict__ gate,
                              const float* __restrict__ gamma, float* __restrict__ out)
{
    const int row = blockIdx.x, t = threadIdx.x;
    const size_t base = (size_t)row * E_ + t * 4;
    float4 ov = *reinterpret_cast<const float4*>(o + base);
    const float4 gv = *reinterpret_cast<const float4*>(gate + base);
    ov.x *= gv.x; ov.y *= gv.y; ov.z *= gv.z; ov.w *= gv.w;
    float s  = ov.x + ov.y + ov.z + ov.w;
    float s2 = ov.x * ov.x + ov.y * ov.y + ov.z * ov.z + ov.w * ov.w;
#pragma unroll
    for (int m = 16; m; m >>= 1) {
        s  += __shfl_xor_sync(0xffffffffu, s,  m);
        s2 += __shfl_xor_sync(0xffffffffu, s2, m);
    }
    __shared__ float sred[2][8];
    const int w = t >> 5, lane = t & 31;
    if (lane == 0) { sred[0][w] = s; sred[1][w] = s2; }
    __syncthreads();
    float st = 0.f, s2t = 0.f;
#pragma unroll
    for (int i = 0; i < 8; i++) { st += sred[0][i]; s2t += sred[1][i]; }
    const float mu  = st * (1.f / E_);
    const float var = s2t * (1.f / E_) - mu * mu;
    const float r   = rsqrtf(var + 1e-5f);
    const float4 gm = *reinterpret_cast<const float4*>(gamma + t * 4);
    float4 res;
    res.x = (ov.x - mu) * r * gm.x;
    res.y = (ov.y - mu) * r * gm.y;
    res.z = (ov.z - mu) * r * gm.z;
    res.w = (ov.w - mu) * r * gm.w;
    *reinterpret_cast<float4*>(out + base) = res;
}

// ---------------- launch ----------------------------------------------------
extern "C" void kernel_launch(void* const* d_in, const int* in_sizes, int n_in,
                              void* d_out, int out_size)
{
    (void)in_sizes; (void)n_in; (void)out_size;
    const float* x   = (const float*)d_in[0];
    const float* llb = (const float*)d_in[1];
    const float* Wq  = (const float*)d_in[2];
    const float* Wk  = (const float*)d_in[3];
    const float* Wv  = (const float*)d_in[4];
    const float* Wf  = (const float*)d_in[5];
    const float* Wb1 = (const float*)d_in[6];
    const float* Wb2 = (const float*)d_in[7];
    const float* Wg1 = (const float*)d_in[8];
    const float* Wg2 = (const float*)d_in[9];
    const float* gamma = (const float*)d_in[10];
    const float* Wo  = (const float*)d_in[11];
    float* out = (float*)d_out;

    float *q, *k, *v, *beta, *gate, *o, *t2, *u, *u2, *fg;
    cudaGetSymbolAddress((void**)&q,    g_q);
    cudaGetSymbolAddress((void**)&k,    g_k);
    cudaGetSymbolAddress((void**)&v,    g_v);
    cudaGetSymbolAddress((void**)&beta, g_beta);
    cudaGetSymbolAddress((void**)&gate, g_gate);
    cudaGetSymbolAddress((void**)&o,    g_o);
    cudaGetSymbolAddress((void**)&t2,   g_t2);
    cudaGetSymbolAddress((void**)&u,    g_u);
    cudaGetSymbolAddress((void**)&u2,   g_u2);
    cudaGetSymbolAddress((void**)&fg,   g_fg);

    cudaFuncSetAttribute(gemm_tf32, cudaFuncAttributeMaxDynamicSharedMemorySize, GEMM_SMEM);

    const dim3 blk(256);

    // low-rank projections: u = x Wb1^T, u2 = x Wg1^T (fused, z=2)
    {
        GemmBatch gb{};
        gb.A[0] = x;   gb.W[0] = Wb1; gb.C[0] = u;  gb.act[0] = 0;
        gb.A[1] = x;   gb.W[1] = Wg1; gb.C[1] = u2; gb.act[1] = 0;
        gemm_tf32<<<dim3(R_/128, ROWS_/128, 2), blk, GEMM_SMEM>>>(gb, ROWS_, R_, E_);
    }
    // qkv projections (fused, z=3)
    {
        GemmBatch gb{};
        gb.A[0] = x; gb.W[0] = Wq; gb.C[0] = q; gb.act[0] = 1;
        gb.A[1] = x; gb.W[1] = Wk; gb.C[1] = k; gb.act[1] = 1;
        gb.A[2] = x; gb.W[2] = Wv; gb.C[2] = v; gb.act[2] = 0;
        gemm_tf32<<<dim3(E_/128, ROWS_/128, 3), blk, GEMM_SMEM>>>(gb, ROWS_, E_, E_);
    }
    fdecay_kernel<<<ROWS_, 256>>>(x, Wf, llb, fg);

    // beta = silu(u Wb2^T), gate = sigmoid(u2 Wg2^T) (fused, z=2)
    {
        GemmBatch gb{};
        gb.A[0] = u;  gb.W[0] = Wb2; gb.C[0] = beta; gb.act[0] = 1;
        gb.A[1] = u2; gb.W[1] = Wg2; gb.C[1] = gate; gb.act[1] = 2;
        gemm_tf32<<<dim3(E_/128, ROWS_/128, 2), blk, GEMM_SMEM>>>(gb, ROWS_, E_, R_);
    }

    householder_kernel<<<ROWS_, 256>>>(q, beta);

    gla_kernel<<<B_ * H_ * 16, 128>>>(q, k, v, fg, o);

    gateln_kernel<<<ROWS_, 256>>>(o, gate, gamma, t2);

    // output projection
    {
        GemmBatch gb{};
        gb.A[0] = t2; gb.W[0] = Wo; gb.C[0] = out; gb.act[0] = 0;
        gemm_tf32<<<dim3(E_/128, ROWS_/128, 1), blk, GEMM_SMEM>>>(gb, ROWS_, E_, E_);
    }
}

// round 7
// speedup vs baseline: 4.0740x; 1.1243x over previous
#include <cuda_runtime.h>
#include <cuda_fp16.h>
#include <math.h>
#include <stdint.h>

#define B_ 2
#define N_ 4096
#define E_ 1024
#define R_ 128
#define H_ 8
#define ROWS_ (B_*N_)   // 8192
#define CH_ 16          // GLA staging depth

// ---------------- scratch (static device allocations; no cudaMalloc) -------
__device__ float g_q   [ROWS_*E_];
__device__ float g_k   [ROWS_*E_];
__device__ float g_v   [ROWS_*E_];
__device__ float g_beta[ROWS_*E_];
__device__ float g_gate[ROWS_*E_];
__device__ float g_o   [ROWS_*E_];
__device__ float g_t2  [ROWS_*E_];
__device__ float g_u   [ROWS_*R_];
__device__ float g_u2  [ROWS_*R_];
__device__ float g_fg  [B_*H_*N_];

// ---------------- helpers ----------------------------------------------------
__device__ __forceinline__ float act_rt(float x, int a) {
    if (a == 1) return x * (1.f / (1.f + __expf(-x)));   // silu
    if (a == 2) return 1.f / (1.f + __expf(-x));          // sigmoid
    return x;
}

__device__ __forceinline__ uint32_t h2pack(float a, float b) {
    __half2 p = __floats2half2_rn(a, b);
    return *reinterpret_cast<uint32_t*>(&p);
}

__device__ __forceinline__ void mma_f16(float c[4], const uint32_t a[4], const uint32_t b[2]) {
    asm volatile(
        "mma.sync.aligned.m16n8k16.row.col.f32.f16.f16.f32 "
        "{%0,%1,%2,%3}, {%4,%5,%6,%7}, {%8,%9}, {%0,%1,%2,%3};"
        : "+f"(c[0]), "+f"(c[1]), "+f"(c[2]), "+f"(c[3])
        : "r"(a[0]), "r"(a[1]), "r"(a[2]), "r"(a[3]), "r"(b[0]), "r"(b[1]));
}

__device__ __forceinline__ void ldsm4(uint32_t& r0, uint32_t& r1, uint32_t& r2, uint32_t& r3,
                                      uint32_t saddr) {
    asm volatile("ldmatrix.sync.aligned.m8n8.x4.shared.b16 {%0,%1,%2,%3}, [%4];"
        : "=r"(r0), "=r"(r1), "=r"(r2), "=r"(r3) : "r"(saddr));
}

__device__ __forceinline__ void cp16(void* smem, const void* gmem) {
    uint32_t s = (uint32_t)__cvta_generic_to_shared(smem);
    asm volatile("cp.async.cg.shared.global [%0], [%1], 16;" :: "r"(s), "l"(gmem));
}

struct GemmBatch {
    const float* A[3];
    const float* W[3];
    float*       C[3];
    int          act[3];
};

// ---------------- fp16 tensor-core NT GEMM ----------------------------------
// C[m,n] = act(sum_k A[m,k]*W[n,k]); M,Nc mult of 128; K mult of 32.
// 256 thr = 8 warps (4m x 2n); warp tile 32x64; K-chunk 32 (2 ksteps of 16).
// fp16 inputs (rounded from fp32), fp32 accumulate. Double-buffered smem.
#define LDSH 40                       // halves per smem row (80B, conflict-free)
#define HBUF (128 * LDSH)             // halves per tensor per buffer
#define GEMM_SMEM (4 * HBUF * 2)      // bytes: 2 tensors x 2 buffers = 40960
__global__ void __launch_bounds__(256, 2) gemm_fp16(GemmBatch gb, int Nc, int K)
{
    extern __shared__ __half hsm[];
    const uint32_t sA = (uint32_t)__cvta_generic_to_shared(hsm);
    const uint32_t sW = sA + 2u * HBUF * 2u;

    const int z = blockIdx.z;
    const float* __restrict__ A = gb.A[z];
    const float* __restrict__ W = gb.W[z];
    float* __restrict__ C = gb.C[z];
    const int ACT = gb.act[z];

    const int t    = threadIdx.x;
    const int warp = t >> 5, lane = t & 31;
    const int bm = blockIdx.y, bn = blockIdx.x;
    const int wm = (warp >> 1) * 32;
    const int wn = (warp & 1) * 64;
    const int gm = lane >> 2, gc = lane & 3;

    float acc[2][8][4];
#pragma unroll
    for (int i = 0; i < 2; i++)
#pragma unroll
        for (int j = 0; j < 8; j++)
#pragma unroll
            for (int l = 0; l < 4; l++) acc[i][j][l] = 0.f;

    const int row  = t >> 1;
    const int half = t & 1;
    const float* Ap = A + (size_t)(bm * 128 + row) * K + half * 16;
    const float* Wp = W + (size_t)(bn * 128 + row) * K + half * 16;
    const uint32_t stByte = (uint32_t)(row * LDSH + half * 16) * 2u;

    // ldmatrix lane-addressing (halves)
    const int aRow = wm + (lane & 15);            // + mt*16
    const int aCol = (lane >> 4) * 8;             // + ks
    const int bRow = wn + ((lane >> 4) << 3) + (lane & 7);   // + p*16
    const int bCol = ((lane >> 3) & 1) * 8;       // + ks

    float4 a4[4], w4[4];
#pragma unroll
    for (int i = 0; i < 4; i++) {                 // prologue: chunk 0
        a4[i] = *reinterpret_cast<const float4*>(Ap + i * 4);
        w4[i] = *reinterpret_cast<const float4*>(Wp + i * 4);
    }

    int buf = 0;
    for (int kt = 0; kt < K; kt += 32, buf ^= 1) {
        const uint32_t aBuf = sA + (uint32_t)buf * HBUF * 2u;
        const uint32_t wBuf = sW + (uint32_t)buf * HBUF * 2u;
        // convert + store staged chunk (16 halves = 2 x v4.b32 per tensor)
        {
            uint32_t ha[8], hw[8];
#pragma unroll
            for (int j = 0; j < 4; j++) {
                ha[2*j]   = h2pack(a4[j].x, a4[j].y);
                ha[2*j+1] = h2pack(a4[j].z, a4[j].w);
                hw[2*j]   = h2pack(w4[j].x, w4[j].y);
                hw[2*j+1] = h2pack(w4[j].z, w4[j].w);
            }
            asm volatile("st.shared.v4.b32 [%0], {%1,%2,%3,%4};"
                :: "r"(aBuf + stByte), "r"(ha[0]), "r"(ha[1]), "r"(ha[2]), "r"(ha[3]) : "memory");
            asm volatile("st.shared.v4.b32 [%0], {%1,%2,%3,%4};"
                :: "r"(aBuf + stByte + 16u), "r"(ha[4]), "r"(ha[5]), "r"(ha[6]), "r"(ha[7]) : "memory");
            asm volatile("st.shared.v4.b32 [%0], {%1,%2,%3,%4};"
                :: "r"(wBuf + stByte), "r"(hw[0]), "r"(hw[1]), "r"(hw[2]), "r"(hw[3]) : "memory");
            asm volatile("st.shared.v4.b32 [%0], {%1,%2,%3,%4};"
                :: "r"(wBuf + stByte + 16u), "r"(hw[4]), "r"(hw[5]), "r"(hw[6]), "r"(hw[7]) : "memory");
        }
        if (kt + 32 < K) {                        // prefetch next chunk
#pragma unroll
            for (int i = 0; i < 4; i++) {
                a4[i] = *reinterpret_cast<const float4*>(Ap + kt + 32 + i * 4);
                w4[i] = *reinterpret_cast<const float4*>(Wp + kt + 32 + i * 4);
            }
        }
        __syncthreads();                          // buf ready for all warps

#pragma unroll
        for (int ks = 0; ks < 32; ks += 16) {
            uint32_t af[2][4];
#pragma unroll
            for (int mt = 0; mt < 2; mt++)
                ldsm4(af[mt][0], af[mt][1], af[mt][2], af[mt][3],
                      aBuf + (uint32_t)((aRow + mt * 16) * LDSH + aCol + ks) * 2u);
            uint32_t bf[8][2];
#pragma unroll
            for (int p = 0; p < 4; p++) {
                uint32_t r0, r1, r2, r3;
                ldsm4(r0, r1, r2, r3,
                      wBuf + (uint32_t)((bRow + p * 16) * LDSH + bCol + ks) * 2u);
                bf[2*p][0]   = r0; bf[2*p][1]   = r1;
                bf[2*p+1][0] = r2; bf[2*p+1][1] = r3;
            }
#pragma unroll
            for (int mt = 0; mt < 2; mt++)
#pragma unroll
                for (int nt = 0; nt < 8; nt++)
                    mma_f16(acc[mt][nt], af[mt], bf[nt]);
        }
        __syncthreads();                          // done reading buf
    }

#pragma unroll
    for (int mt = 0; mt < 2; mt++) {
        const int row0 = bm * 128 + wm + mt * 16 + gm;
#pragma unroll
        for (int nt = 0; nt < 8; nt++) {
            const int col = bn * 128 + wn + nt * 8 + 2 * gc;
            float2 lo, hi;
            lo.x = act_rt(acc[mt][nt][0], ACT); lo.y = act_rt(acc[mt][nt][1], ACT);
            hi.x = act_rt(acc[mt][nt][2], ACT); hi.y = act_rt(acc[mt][nt][3], ACT);
            *reinterpret_cast<float2*>(C + (size_t)row0 * Nc + col)       = lo;
            *reinterpret_cast<float2*>(C + (size_t)(row0 + 8) * Nc + col) = hi;
        }
    }
}

// ---------------- f projection + decay gate ---------------------------------
__global__ void fdecay_kernel(const float* __restrict__ x, const float* __restrict__ Wf,
                              const float* __restrict__ llb, float* __restrict__ fgout)
{
    const int row  = blockIdx.x;
    const int h    = threadIdx.x >> 5;
    const int lane = threadIdx.x & 31;
    const float* xr = x  + (size_t)row * E_;
    const float* wr = Wf + (size_t)h   * E_;
    float s = 0.f;
    for (int e = lane; e < E_; e += 32) s = fmaf(xr[e], wr[e], s);
#pragma unroll
    for (int m = 16; m; m >>= 1) s += __shfl_xor_sync(0xffffffffu, s, m);
    if (lane == 0) {
        const float lb  = __expf(llb[h]);
        const float fgv = lb + (1.f - lb) * (1.f / (1.f + __expf(-s)));
        const int b = row >> 12;
        const int n = row & (N_ - 1);
        fgout[((size_t)b * H_ + h) * N_ + n] = fgv;
    }
}

// ---------------- householder: q -= 2*(q.beta)/(beta.beta+eps) * beta -------
__global__ void householder_kernel(float* __restrict__ q, const float* __restrict__ beta)
{
    const int row = blockIdx.x, t = threadIdx.x;
    const size_t base = (size_t)row * E_ + t * 4;
    const float4 b4 = *reinterpret_cast<const float4*>(beta + base);
    float4 q4 = *reinterpret_cast<float4*>(q + base);
    float ss = b4.x * b4.x + b4.y * b4.y + b4.z * b4.z + b4.w * b4.w;
    float dq = q4.x * b4.x + q4.y * b4.y + q4.z * b4.z + q4.w * b4.w;
#pragma unroll
    for (int m = 16; m; m >>= 1) {
        ss += __shfl_xor_sync(0xffffffffu, ss, m);
        dq += __shfl_xor_sync(0xffffffffu, dq, m);
    }
    __shared__ float sred[2][8];
    const int w = t >> 5, lane = t & 31;
    if (lane == 0) { sred[0][w] = ss; sred[1][w] = dq; }
    __syncthreads();
    float sst = 0.f, dqt = 0.f;
#pragma unroll
    for (int i = 0; i < 8; i++) { sst += sred[0][i]; dqt += sred[1][i]; }
    const float coef = 2.f * dqt / (sst + 1e-12f);
    q4.x -= coef * b4.x; q4.y -= coef * b4.y;
    q4.z -= coef * b4.z; q4.w -= coef * b4.w;
    *reinterpret_cast<float4*>(q + base) = q4;
}

// ---------------- GLA recurrence (cp.async 16-step staged) ------------------
__global__ void __launch_bounds__(128) gla_kernel(
    const float* __restrict__ q, const float* __restrict__ k,
    const float* __restrict__ v, const float* __restrict__ fg,
    float* __restrict__ o)
{
    const int bid = blockIdx.x;
    const int vg  = bid & 15;
    const int bh  = bid >> 4;
    const int b   = bh >> 3, h = bh & 7;
    const int t   = threadIdx.x;
    const int col = t >> 4, kg = t & 15;

    __shared__ alignas(16) float sk[2][CH_][128];
    __shared__ alignas(16) float sq[2][CH_][128];
    __shared__ alignas(16) float sv[2][CH_][8];
    __shared__ alignas(16) float sg[2][CH_];

    const size_t rowbase = (size_t)b * N_ * E_ + (size_t)h * R_;
    const float* kb  = k + rowbase;
    const float* qb  = q + rowbase;
    const float* vb  = v + rowbase + vg * 8;
    const float* fgb = fg + (size_t)bh * N_;
    float* ob = o + rowbase + vg * 8 + col;

    auto issue_stage = [&](int st, int n0) {
#pragma unroll
        for (int c = 0; c < 4; c++) {
            const int idx  = c * 128 + t;
            const int step = idx >> 5;
            const int part = idx & 31;
            cp16(&sk[st][step][part * 4], kb + (size_t)(n0 + step) * E_ + part * 4);
            cp16(&sq[st][step][part * 4], qb + (size_t)(n0 + step) * E_ + part * 4);
        }
        if (t < 32) {
            const int step = t >> 1, part = t & 1;
            cp16(&sv[st][step][part * 4], vb + (size_t)(n0 + step) * E_ + part * 4);
        }
        if (t < 4)
            cp16(&sg[st][t * 4], fgb + n0 + t * 4);
    };

    float S[8];
#pragma unroll
    for (int i = 0; i < 8; i++) S[i] = 0.f;

    issue_stage(0, 0);
    asm volatile("cp.async.commit_group;" ::: "memory");

    const float scale = rsqrtf((float)R_);
    for (int blk = 0; blk < N_ / CH_; blk++) {
        const int cur = blk & 1, nxt = cur ^ 1;
        if (blk + 1 < N_ / CH_) issue_stage(nxt, (blk + 1) * CH_);
        asm volatile("cp.async.commit_group;" ::: "memory");
        asm volatile("cp.async.wait_group 1;" ::: "memory");
        __syncthreads();
#pragma unroll 4
        for (int s = 0; s < CH_; s++) {
            const float eg   = sg[cur][s];
            const float vval = sv[cur][s][col];
            const float4 k4a = *reinterpret_cast<const float4*>(&sk[cur][s][kg * 8]);
            const float4 q4a = *reinterpret_cast<const float4*>(&sq[cur][s][kg * 8]);
            const float4 k4b = *reinterpret_cast<const float4*>(&sk[cur][s][kg * 8 + 4]);
            const float4 q4b = *reinterpret_cast<const float4*>(&sq[cur][s][kg * 8 + 4]);
            float a0 = 0.f, a1 = 0.f;
            S[0] = fmaf(S[0], eg, k4a.x * vval); a0 = fmaf(q4a.x, S[0], a0);
            S[1] = fmaf(S[1], eg, k4a.y * vval); a0 = fmaf(q4a.y, S[1], a0);
            S[2] = fmaf(S[2], eg, k4a.z * vval); a0 = fmaf(q4a.z, S[2], a0);
            S[3] = fmaf(S[3], eg, k4a.w * vval); a0 = fmaf(q4a.w, S[3], a0);
            S[4] = fmaf(S[4], eg, k4b.x * vval); a1 = fmaf(q4b.x, S[4], a1);
            S[5] = fmaf(S[5], eg, k4b.y * vval); a1 = fmaf(q4b.y, S[5], a1);
            S[6] = fmaf(S[6], eg, k4b.z * vval); a1 = fmaf(q4b.z, S[6], a1);
            S[7] = fmaf(S[7], eg, k4b.w * vval); a1 = fmaf(q4b.w, S[7], a1);
            float acc = a0 + a1;
            acc += __shfl_xor_sync(0xffffffffu, acc, 1);
            acc += __shfl_xor_sync(0xffffffffu, acc, 2);
            acc += __shfl_xor_sync(0xffffffffu, acc, 4);
            acc += __shfl_xor_sync(0xffffffffu, acc, 8);
            if (kg == 0) ob[(size_t)(blk * CH_ + s) * E_] = acc * scale;
        }
        __syncthreads();
    }
}

// ---------------- gate * o, then LayerNorm (weight only) --------------------
__global__ void gateln_kernel(const float* __restrict__ o, const float* __restrict__ gate,
                              const float* __restrict__ gamma, float* __restrict__ out)
{
    const int row = blockIdx.x, t = threadIdx.x;
    const size_t base = (size_t)row * E_ + t * 4;
    float4 ov = *reinterpret_cast<const float4*>(o + base);
    const float4 gv = *reinterpret_cast<const float4*>(gate + base);
    ov.x *= gv.x; ov.y *= gv.y; ov.z *= gv.z; ov.w *= gv.w;
    float s  = ov.x + ov.y + ov.z + ov.w;
    float s2 = ov.x * ov.x + ov.y * ov.y + ov.z * ov.z + ov.w * ov.w;
#pragma unroll
    for (int m = 16; m; m >>= 1) {
        s  += __shfl_xor_sync(0xffffffffu, s,  m);
        s2 += __shfl_xor_sync(0xffffffffu, s2, m);
    }
    __shared__ float sred[2][8];
    const int w = t >> 5, lane = t & 31;
    if (lane == 0) { sred[0][w] = s; sred[1][w] = s2; }
    __syncthreads();
    float st = 0.f, s2t = 0.f;
#pragma unroll
    for (int i = 0; i < 8; i++) { st += sred[0][i]; s2t += sred[1][i]; }
    const float mu  = st * (1.f / E_);
    const float var = s2t * (1.f / E_) - mu * mu;
    const float r   = rsqrtf(var + 1e-5f);
    const float4 gm = *reinterpret_cast<const float4*>(gamma + t * 4);
    float4 res;
    res.x = (ov.x - mu) * r * gm.x;
    res.y = (ov.y - mu) * r * gm.y;
    res.z = (ov.z - mu) * r * gm.z;
    res.w = (ov.w - mu) * r * gm.w;
    *reinterpret_cast<float4*>(out + base) = res;
}

// ---------------- launch ----------------------------------------------------
extern "C" void kernel_launch(void* const* d_in, const int* in_sizes, int n_in,
                              void* d_out, int out_size)
{
    (void)in_sizes; (void)n_in; (void)out_size;
    const float* x   = (const float*)d_in[0];
    const float* llb = (const float*)d_in[1];
    const float* Wq  = (const float*)d_in[2];
    const float* Wk  = (const float*)d_in[3];
    const float* Wv  = (const float*)d_in[4];
    const float* Wf  = (const float*)d_in[5];
    const float* Wb1 = (const float*)d_in[6];
    const float* Wb2 = (const float*)d_in[7];
    const float* Wg1 = (const float*)d_in[8];
    const float* Wg2 = (const float*)d_in[9];
    const float* gamma = (const float*)d_in[10];
    const float* Wo  = (const float*)d_in[11];
    float* out = (float*)d_out;

    float *q, *k, *v, *beta, *gate, *o, *t2, *u, *u2, *fg;
    cudaGetSymbolAddress((void**)&q,    g_q);
    cudaGetSymbolAddress((void**)&k,    g_k);
    cudaGetSymbolAddress((void**)&v,    g_v);
    cudaGetSymbolAddress((void**)&beta, g_beta);
    cudaGetSymbolAddress((void**)&gate, g_gate);
    cudaGetSymbolAddress((void**)&o,    g_o);
    cudaGetSymbolAddress((void**)&t2,   g_t2);
    cudaGetSymbolAddress((void**)&u,    g_u);
    cudaGetSymbolAddress((void**)&u2,   g_u2);
    cudaGetSymbolAddress((void**)&fg,   g_fg);

    cudaFuncSetAttribute(gemm_fp16, cudaFuncAttributeMaxDynamicSharedMemorySize, GEMM_SMEM);

    const dim3 blk(256);

    // low-rank projections: u = x Wb1^T, u2 = x Wg1^T (fused, z=2)
    {
        GemmBatch gb{};
        gb.A[0] = x;   gb.W[0] = Wb1; gb.C[0] = u;  gb.act[0] = 0;
        gb.A[1] = x;   gb.W[1] = Wg1; gb.C[1] = u2; gb.act[1] = 0;
        gemm_fp16<<<dim3(R_/128, ROWS_/128, 2), blk, GEMM_SMEM>>>(gb, R_, E_);
    }
    // qkv projections (fused, z=3)
    {
        GemmBatch gb{};
        gb.A[0] = x; gb.W[0] = Wq; gb.C[0] = q; gb.act[0] = 1;
        gb.A[1] = x; gb.W[1] = Wk; gb.C[1] = k; gb.act[1] = 1;
        gb.A[2] = x; gb.W[2] = Wv; gb.C[2] = v; gb.act[2] = 0;
        gemm_fp16<<<dim3(E_/128, ROWS_/128, 3), blk, GEMM_SMEM>>>(gb, E_, E_);
    }
    fdecay_kernel<<<ROWS_, 256>>>(x, Wf, llb, fg);

    // beta = silu(u Wb2^T), gate = sigmoid(u2 Wg2^T) (fused, z=2)
    {
        GemmBatch gb{};
        gb.A[0] = u;  gb.W[0] = Wb2; gb.C[0] = beta; gb.act[0] = 1;
        gb.A[1] = u2; gb.W[1] = Wg2; gb.C[1] = gate; gb.act[1] = 2;
        gemm_fp16<<<dim3(E_/128, ROWS_/128, 2), blk, GEMM_SMEM>>>(gb, E_, R_);
    }

    householder_kernel<<<ROWS_, 256>>>(q, beta);

    gla_kernel<<<B_ * H_ * 16, 128>>>(q, k, v, fg, o);

    gateln_kernel<<<ROWS_, 256>>>(o, gate, gamma, t2);

    // output projection
    {
        GemmBatch gb{};
        gb.A[0] = t2; gb.W[0] = Wo; gb.C[0] = out; gb.act[0] = 0;
        gemm_fp16<<<dim3(E_/128, ROWS_/128, 1), blk, GEMM_SMEM>>>(gb, E_, E_);
    }
}

// round 8
// speedup vs baseline: 4.5502x; 1.1169x over previous
#include <cuda_runtime.h>
#include <cuda_fp16.h>
#include <math.h>
#include <stdint.h>

#define B_ 2
#define N_ 4096
#define E_ 1024
#define R_ 128
#define H_ 8
#define ROWS_ (B_*N_)   // 8192
#define CH_ 16          // GLA staging depth

// ---------------- scratch (static device allocations; no cudaMalloc) -------
__device__ float g_q   [ROWS_*E_];
__device__ float g_k   [ROWS_*E_];
__device__ float g_v   [ROWS_*E_];
__device__ float g_beta[ROWS_*E_];
__device__ float g_gate[ROWS_*E_];
__device__ float g_o   [ROWS_*E_];
__device__ float g_fg  [B_*H_*N_];
// fp16 pipeline buffers
__device__ __half g_xh  [ROWS_*E_];
__device__ __half g_uh  [ROWS_*R_];
__device__ __half g_u2h [ROWS_*R_];
__device__ __half g_t2h [ROWS_*E_];
__device__ __half g_wqh [E_*E_];
__device__ __half g_wkh [E_*E_];
__device__ __half g_wvh [E_*E_];
__device__ __half g_woh [E_*E_];
__device__ __half g_wb1h[R_*E_];
__device__ __half g_wb2h[E_*R_];
__device__ __half g_wg1h[R_*E_];
__device__ __half g_wg2h[E_*R_];

// ---------------- helpers ----------------------------------------------------
__device__ __forceinline__ float act_rt(float x, int a) {
    if (a == 1) return x * (1.f / (1.f + __expf(-x)));   // silu
    if (a == 2) return 1.f / (1.f + __expf(-x));          // sigmoid
    return x;
}

__device__ __forceinline__ void mma_f16(float c[4], const uint32_t a[4], const uint32_t b[2]) {
    asm volatile(
        "mma.sync.aligned.m16n8k16.row.col.f32.f16.f16.f32 "
        "{%0,%1,%2,%3}, {%4,%5,%6,%7}, {%8,%9}, {%0,%1,%2,%3};"
        : "+f"(c[0]), "+f"(c[1]), "+f"(c[2]), "+f"(c[3])
        : "r"(a[0]), "r"(a[1]), "r"(a[2]), "r"(a[3]), "r"(b[0]), "r"(b[1]));
}

__device__ __forceinline__ void ldsm4(uint32_t& r0, uint32_t& r1, uint32_t& r2, uint32_t& r3,
                                      uint32_t saddr) {
    asm volatile("ldmatrix.sync.aligned.m8n8.x4.shared.b16 {%0,%1,%2,%3}, [%4];"
        : "=r"(r0), "=r"(r1), "=r"(r2), "=r"(r3) : "r"(saddr));
}

__device__ __forceinline__ void cp16(void* smem, const void* gmem) {
    uint32_t s = (uint32_t)__cvta_generic_to_shared(smem);
    asm volatile("cp.async.cg.shared.global [%0], [%1], 16;" :: "r"(s), "l"(gmem));
}
__device__ __forceinline__ void cp16u(uint32_t saddr, const void* gmem) {
    asm volatile("cp.async.cg.shared.global [%0], [%1], 16;" :: "r"(saddr), "l"(gmem));
}

// ---------------- fp32 -> fp16 bulk conversion ------------------------------
__global__ void f2h_kernel(const float* __restrict__ in, __half* __restrict__ out, int n)
{
    const int i = (blockIdx.x * blockDim.x + threadIdx.x) * 8;
    if (i >= n) return;
    const float4 a = *reinterpret_cast<const float4*>(in + i);
    const float4 b = *reinterpret_cast<const float4*>(in + i + 4);
    __half2 h[4];
    h[0] = __floats2half2_rn(a.x, a.y); h[1] = __floats2half2_rn(a.z, a.w);
    h[2] = __floats2half2_rn(b.x, b.y); h[3] = __floats2half2_rn(b.z, b.w);
    *reinterpret_cast<uint4*>(out + i) = *reinterpret_cast<uint4*>(h);
}

struct GemmBatch {
    const __half* A[3];
    const __half* W[3];
    void*         C[3];
    int           act[3];
    int           oh[3];     // 1 = fp16 output, 0 = fp32 output
};

// ---------------- fp16 tensor-core NT GEMM (cp.async pipelined) -------------
// C[m,n] = act(sum_k A[m,k]*W[n,k]); fp16 in, fp32 acc; M,Nc mult 128; K mult 64.
// 256 thr = 8 warps (4m x 2n); warp tile 32x64; K-chunk 64 halves; 2 stages.
#define LDSH 72                         // halves per smem row (144B, conflict-free)
#define STAGE_B (128 * LDSH * 2)        // bytes per tensor per stage = 18432
#define NSTG 2
#define GEMM_SMEM (2 * NSTG * STAGE_B)  // 73728
__global__ void __launch_bounds__(256, 2) gemm_fp16(GemmBatch gb, int Nc, int K)
{
    extern __shared__ char hsm[];
    const uint32_t sA = (uint32_t)__cvta_generic_to_shared(hsm);
    const uint32_t sW = sA + NSTG * STAGE_B;

    const int z = blockIdx.z;
    const __half* __restrict__ A = gb.A[z];
    const __half* __restrict__ W = gb.W[z];
    void* Cv = gb.C[z];
    const int ACT = gb.act[z];
    const int OH  = gb.oh[z];

    const int t    = threadIdx.x;
    const int warp = t >> 5, lane = t & 31;
    const int bm = blockIdx.y, bn = blockIdx.x;
    const int wm = (warp >> 1) * 32;
    const int wn = (warp & 1) * 64;
    const int gm = lane >> 2, gc = lane & 3;

    float acc[2][8][4];
#pragma unroll
    for (int i = 0; i < 2; i++)
#pragma unroll
        for (int j = 0; j < 8; j++)
#pragma unroll
            for (int l = 0; l < 4; l++) acc[i][j][l] = 0.f;

    const int row  = t >> 1;
    const int half = t & 1;
    const __half* Ap = A + (size_t)(bm * 128 + row) * K + half * 32;
    const __half* Wp = W + (size_t)(bn * 128 + row) * K + half * 32;
    const uint32_t stOff = (uint32_t)(row * LDSH + half * 32) * 2u;

    const int nc = K >> 6;      // chunks of 64 halves
    auto issue = [&](int s) {
        if (s < nc) {
            const uint32_t ab = sA + (uint32_t)(s & (NSTG - 1)) * STAGE_B + stOff;
            const uint32_t wb = sW + (uint32_t)(s & (NSTG - 1)) * STAGE_B + stOff;
            const __half* Ag = Ap + s * 64;
            const __half* Wg = Wp + s * 64;
#pragma unroll
            for (int j = 0; j < 4; j++) {
                cp16u(ab + j * 16u, Ag + j * 8);
                cp16u(wb + j * 16u, Wg + j * 8);
            }
        }
        asm volatile("cp.async.commit_group;" ::: "memory");
    };

    issue(0);

    // ldmatrix lane addressing (halves)
    const int aRow = wm + (lane & 15);
    const int aCol = (lane >> 4) * 8;
    const int bRow = wn + ((lane >> 4) << 3) + (lane & 7);
    const int bCol = ((lane >> 3) & 1) * 8;

    for (int i = 0; i < nc; i++) {
        asm volatile("cp.async.wait_group 0;" ::: "memory");
        __syncthreads();
        issue(i + 1);
        const uint32_t aBuf = sA + (uint32_t)(i & (NSTG - 1)) * STAGE_B;
        const uint32_t wBuf = sW + (uint32_t)(i & (NSTG - 1)) * STAGE_B;
#pragma unroll
        for (int ks = 0; ks < 64; ks += 16) {
            uint32_t af[2][4];
#pragma unroll
            for (int mt = 0; mt < 2; mt++)
                ldsm4(af[mt][0], af[mt][1], af[mt][2], af[mt][3],
                      aBuf + (uint32_t)((aRow + mt * 16) * LDSH + aCol + ks) * 2u);
            uint32_t bf[8][2];
#pragma unroll
            for (int p = 0; p < 4; p++) {
                uint32_t r0, r1, r2, r3;
                ldsm4(r0, r1, r2, r3,
                      wBuf + (uint32_t)((bRow + p * 16) * LDSH + bCol + ks) * 2u);
                bf[2*p][0]   = r0; bf[2*p][1]   = r1;
                bf[2*p+1][0] = r2; bf[2*p+1][1] = r3;
            }
#pragma unroll
            for (int mt = 0; mt < 2; mt++)
#pragma unroll
                for (int nt = 0; nt < 8; nt++)
                    mma_f16(acc[mt][nt], af[mt], bf[nt]);
        }
        __syncthreads();
    }

#pragma unroll
    for (int mt = 0; mt < 2; mt++) {
        const int row0 = bm * 128 + wm + mt * 16 + gm;
#pragma unroll
        for (int nt = 0; nt < 8; nt++) {
            const int col = bn * 128 + wn + nt * 8 + 2 * gc;
            float v0 = act_rt(acc[mt][nt][0], ACT), v1 = act_rt(acc[mt][nt][1], ACT);
            float v2 = act_rt(acc[mt][nt][2], ACT), v3 = act_rt(acc[mt][nt][3], ACT);
            if (OH) {
                __half* Ch = (__half*)Cv;
                *reinterpret_cast<__half2*>(Ch + (size_t)row0 * Nc + col) =
                    __floats2half2_rn(v0, v1);
                *reinterpret_cast<__half2*>(Ch + (size_t)(row0 + 8) * Nc + col) =
                    __floats2half2_rn(v2, v3);
            } else {
                float* Cf = (float*)Cv;
                *reinterpret_cast<float2*>(Cf + (size_t)row0 * Nc + col)       = make_float2(v0, v1);
                *reinterpret_cast<float2*>(Cf + (size_t)(row0 + 8) * Nc + col) = make_float2(v2, v3);
            }
        }
    }
}

// ---------------- f projection + decay gate ---------------------------------
__global__ void fdecay_kernel(const float* __restrict__ x, const float* __restrict__ Wf,
                              const float* __restrict__ llb, float* __restrict__ fgout)
{
    const int row  = blockIdx.x;
    const int h    = threadIdx.x >> 5;
    const int lane = threadIdx.x & 31;
    const float* xr = x  + (size_t)row * E_;
    const float* wr = Wf + (size_t)h   * E_;
    float s = 0.f;
    for (int e = lane; e < E_; e += 32) s = fmaf(xr[e], wr[e], s);
#pragma unroll
    for (int m = 16; m; m >>= 1) s += __shfl_xor_sync(0xffffffffu, s, m);
    if (lane == 0) {
        const float lb  = __expf(llb[h]);
        const float fgv = lb + (1.f - lb) * (1.f / (1.f + __expf(-s)));
        const int b = row >> 12;
        const int n = row & (N_ - 1);
        fgout[((size_t)b * H_ + h) * N_ + n] = fgv;
    }
}

// ---------------- householder: q -= 2*(q.beta)/(beta.beta+eps) * beta -------
__global__ void householder_kernel(float* __restrict__ q, const float* __restrict__ beta)
{
    const int row = blockIdx.x, t = threadIdx.x;
    const size_t base = (size_t)row * E_ + t * 4;
    const float4 b4 = *reinterpret_cast<const float4*>(beta + base);
    float4 q4 = *reinterpret_cast<float4*>(q + base);
    float ss = b4.x * b4.x + b4.y * b4.y + b4.z * b4.z + b4.w * b4.w;
    float dq = q4.x * b4.x + q4.y * b4.y + q4.z * b4.z + q4.w * b4.w;
#pragma unroll
    for (int m = 16; m; m >>= 1) {
        ss += __shfl_xor_sync(0xffffffffu, ss, m);
        dq += __shfl_xor_sync(0xffffffffu, dq, m);
    }
    __shared__ float sred[2][8];
    const int w = t >> 5, lane = t & 31;
    if (lane == 0) { sred[0][w] = ss; sred[1][w] = dq; }
    __syncthreads();
    float sst = 0.f, dqt = 0.f;
#pragma unroll
    for (int i = 0; i < 8; i++) { sst += sred[0][i]; dqt += sred[1][i]; }
    const float coef = 2.f * dqt / (sst + 1e-12f);
    q4.x -= coef * b4.x; q4.y -= coef * b4.y;
    q4.z -= coef * b4.z; q4.w -= coef * b4.w;
    *reinterpret_cast<float4*>(q + base) = q4;
}

// ---------------- GLA recurrence (cp.async 16-step staged) ------------------
__global__ void __launch_bounds__(128) gla_kernel(
    const float* __restrict__ q, const float* __restrict__ k,
    const float* __restrict__ v, const float* __restrict__ fg,
    float* __restrict__ o)
{
    const int bid = blockIdx.x;
    const int vg  = bid & 15;
    const int bh  = bid >> 4;
    const int b   = bh >> 3, h = bh & 7;
    const int t   = threadIdx.x;
    const int col = t >> 4, kg = t & 15;

    __shared__ alignas(16) float sk[2][CH_][128];
    __shared__ alignas(16) float sq[2][CH_][128];
    __shared__ alignas(16) float sv[2][CH_][8];
    __shared__ alignas(16) float sg[2][CH_];

    const size_t rowbase = (size_t)b * N_ * E_ + (size_t)h * R_;
    const float* kb  = k + rowbase;
    const float* qb  = q + rowbase;
    const float* vb  = v + rowbase + vg * 8;
    const float* fgb = fg + (size_t)bh * N_;
    float* ob = o + rowbase + vg * 8 + col;

    auto issue_stage = [&](int st, int n0) {
#pragma unroll
        for (int c = 0; c < 4; c++) {
            const int idx  = c * 128 + t;
            const int step = idx >> 5;
            const int part = idx & 31;
            cp16(&sk[st][step][part * 4], kb + (size_t)(n0 + step) * E_ + part * 4);
            cp16(&sq[st][step][part * 4], qb + (size_t)(n0 + step) * E_ + part * 4);
        }
        if (t < 32) {
            const int step = t >> 1, part = t & 1;
            cp16(&sv[st][step][part * 4], vb + (size_t)(n0 + step) * E_ + part * 4);
        }
        if (t < 4)
            cp16(&sg[st][t * 4], fgb + n0 + t * 4);
    };

    float S[8];
#pragma unroll
    for (int i = 0; i < 8; i++) S[i] = 0.f;

    issue_stage(0, 0);
    asm volatile("cp.async.commit_group;" ::: "memory");

    const float scale = rsqrtf((float)R_);
    for (int blk = 0; blk < N_ / CH_; blk++) {
        const int cur = blk & 1, nxt = cur ^ 1;
        if (blk + 1 < N_ / CH_) issue_stage(nxt, (blk + 1) * CH_);
        asm volatile("cp.async.commit_group;" ::: "memory");
        asm volatile("cp.async.wait_group 1;" ::: "memory");
        __syncthreads();
#pragma unroll 4
        for (int s = 0; s < CH_; s++) {
            const float eg   = sg[cur][s];
            const float vval = sv[cur][s][col];
            const float4 k4a = *reinterpret_cast<const float4*>(&sk[cur][s][kg * 8]);
            const float4 q4a = *reinterpret_cast<const float4*>(&sq[cur][s][kg * 8]);
            const float4 k4b = *reinterpret_cast<const float4*>(&sk[cur][s][kg * 8 + 4]);
            const float4 q4b = *reinterpret_cast<const float4*>(&sq[cur][s][kg * 8 + 4]);
            float a0 = 0.f, a1 = 0.f;
            S[0] = fmaf(S[0], eg, k4a.x * vval); a0 = fmaf(q4a.x, S[0], a0);
            S[1] = fmaf(S[1], eg, k4a.y * vval); a0 = fmaf(q4a.y, S[1], a0);
            S[2] = fmaf(S[2], eg, k4a.z * vval); a0 = fmaf(q4a.z, S[2], a0);
            S[3] = fmaf(S[3], eg, k4a.w * vval); a0 = fmaf(q4a.w, S[3], a0);
            S[4] = fmaf(S[4], eg, k4b.x * vval); a1 = fmaf(q4b.x, S[4], a1);
            S[5] = fmaf(S[5], eg, k4b.y * vval); a1 = fmaf(q4b.y, S[5], a1);
            S[6] = fmaf(S[6], eg, k4b.z * vval); a1 = fmaf(q4b.z, S[6], a1);
            S[7] = fmaf(S[7], eg, k4b.w * vval); a1 = fmaf(q4b.w, S[7], a1);
            float acc = a0 + a1;
            acc += __shfl_xor_sync(0xffffffffu, acc, 1);
            acc += __shfl_xor_sync(0xffffffffu, acc, 2);
            acc += __shfl_xor_sync(0xffffffffu, acc, 4);
            acc += __shfl_xor_sync(0xffffffffu, acc, 8);
            if (kg == 0) ob[(size_t)(blk * CH_ + s) * E_] = acc * scale;
        }
        __syncthreads();
    }
}

// ---------------- gate * o, LayerNorm, write fp16 ---------------------------
__global__ void gateln_kernel(const float* __restrict__ o, const float* __restrict__ gate,
                              const float* __restrict__ gamma, __half* __restrict__ out)
{
    const int row = blockIdx.x, t = threadIdx.x;
    const size_t base = (size_t)row * E_ + t * 4;
    float4 ov = *reinterpret_cast<const float4*>(o + base);
    const float4 gv = *reinterpret_cast<const float4*>(gate + base);
    ov.x *= gv.x; ov.y *= gv.y; ov.z *= gv.z; ov.w *= gv.w;
    float s  = ov.x + ov.y + ov.z + ov.w;
    float s2 = ov.x * ov.x + ov.y * ov.y + ov.z * ov.z + ov.w * ov.w;
#pragma unroll
    for (int m = 16; m; m >>= 1) {
        s  += __shfl_xor_sync(0xffffffffu, s,  m);
        s2 += __shfl_xor_sync(0xffffffffu, s2, m);
    }
    __shared__ float sred[2][8];
    const int w = t >> 5, lane = t & 31;
    if (lane == 0) { sred[0][w] = s; sred[1][w] = s2; }
    __syncthreads();
    float st = 0.f, s2t = 0.f;
#pragma unroll
    for (int i = 0; i < 8; i++) { st += sred[0][i]; s2t += sred[1][i]; }
    const float mu  = st * (1.f / E_);
    const float var = s2t * (1.f / E_) - mu * mu;
    const float r   = rsqrtf(var + 1e-5f);
    const float4 gm = *reinterpret_cast<const float4*>(gamma + t * 4);
    __half2 h0 = __floats2half2_rn((ov.x - mu) * r * gm.x, (ov.y - mu) * r * gm.y);
    __half2 h1 = __floats2half2_rn((ov.z - mu) * r * gm.z, (ov.w - mu) * r * gm.w);
    *reinterpret_cast<__half2*>(out + base)     = h0;
    *reinterpret_cast<__half2*>(out + base + 2) = h1;
}

// ---------------- launch ----------------------------------------------------
extern "C" void kernel_launch(void* const* d_in, const int* in_sizes, int n_in,
                              void* d_out, int out_size)
{
    (void)in_sizes; (void)n_in; (void)out_size;
    const float* x   = (const float*)d_in[0];
    const float* llb = (const float*)d_in[1];
    const float* Wq  = (const float*)d_in[2];
    const float* Wk  = (const float*)d_in[3];
    const float* Wv  = (const float*)d_in[4];
    const float* Wf  = (const float*)d_in[5];
    const float* Wb1 = (const float*)d_in[6];
    const float* Wb2 = (const float*)d_in[7];
    const float* Wg1 = (const float*)d_in[8];
    const float* Wg2 = (const float*)d_in[9];
    const float* gamma = (const float*)d_in[10];
    const float* Wo  = (const float*)d_in[11];
    float* out = (float*)d_out;

    float *q, *k, *v, *beta, *gate, *o, *fg;
    __half *xh, *uh, *u2h, *t2h, *wqh, *wkh, *wvh, *woh, *wb1h, *wb2h, *wg1h, *wg2h;
    cudaGetSymbolAddress((void**)&q,    g_q);
    cudaGetSymbolAddress((void**)&k,    g_k);
    cudaGetSymbolAddress((void**)&v,    g_v);
    cudaGetSymbolAddress((void**)&beta, g_beta);
    cudaGetSymbolAddress((void**)&gate, g_gate);
    cudaGetSymbolAddress((void**)&o,    g_o);
    cudaGetSymbolAddress((void**)&fg,   g_fg);
    cudaGetSymbolAddress((void**)&xh,   g_xh);
    cudaGetSymbolAddress((void**)&uh,   g_uh);
    cudaGetSymbolAddress((void**)&u2h,  g_u2h);
    cudaGetSymbolAddress((void**)&t2h,  g_t2h);
    cudaGetSymbolAddress((void**)&wqh,  g_wqh);
    cudaGetSymbolAddress((void**)&wkh,  g_wkh);
    cudaGetSymbolAddress((void**)&wvh,  g_wvh);
    cudaGetSymbolAddress((void**)&woh,  g_woh);
    cudaGetSymbolAddress((void**)&wb1h, g_wb1h);
    cudaGetSymbolAddress((void**)&wb2h, g_wb2h);
    cudaGetSymbolAddress((void**)&wg1h, g_wg1h);
    cudaGetSymbolAddress((void**)&wg2h, g_wg2h);

    cudaFuncSetAttribute(gemm_fp16, cudaFuncAttributeMaxDynamicSharedMemorySize, GEMM_SMEM);

    // fp32 -> fp16 conversions (x + 8 weight matrices)
    auto conv = [&](const float* src, __half* dst, int n) {
        f2h_kernel<<<(n / 8 + 255) / 256, 256>>>(src, dst, n);
    };
    conv(x,   xh,   ROWS_ * E_);
    conv(Wq,  wqh,  E_ * E_);
    conv(Wk,  wkh,  E_ * E_);
    conv(Wv,  wvh,  E_ * E_);
    conv(Wo,  woh,  E_ * E_);
    conv(Wb1, wb1h, R_ * E_);
    conv(Wb2, wb2h, E_ * R_);
    conv(Wg1, wg1h, R_ * E_);
    conv(Wg2, wg2h, E_ * R_);

    const dim3 blk(256);

    // low-rank projections: u = x Wb1^T, u2 = x Wg1^T (fp16 out, fused z=2)
    {
        GemmBatch gb{};
        gb.A[0] = xh; gb.W[0] = wb1h; gb.C[0] = uh;  gb.act[0] = 0; gb.oh[0] = 1;
        gb.A[1] = xh; gb.W[1] = wg1h; gb.C[1] = u2h; gb.act[1] = 0; gb.oh[1] = 1;
        gemm_fp16<<<dim3(R_/128, ROWS_/128, 2), blk, GEMM_SMEM>>>(gb, R_, E_);
    }
    // qkv projections (fp32 out, fused z=3)
    {
        GemmBatch gb{};
        gb.A[0] = xh; gb.W[0] = wqh; gb.C[0] = q; gb.act[0] = 1; gb.oh[0] = 0;
        gb.A[1] = xh; gb.W[1] = wkh; gb.C[1] = k; gb.act[1] = 1; gb.oh[1] = 0;
        gb.A[2] = xh; gb.W[2] = wvh; gb.C[2] = v; gb.act[2] = 0; gb.oh[2] = 0;
        gemm_fp16<<<dim3(E_/128, ROWS_/128, 3), blk, GEMM_SMEM>>>(gb, E_, E_);
    }
    fdecay_kernel<<<ROWS_, 256>>>(x, Wf, llb, fg);

    // beta = silu(u Wb2^T), gate = sigmoid(u2 Wg2^T) (fp32 out, fused z=2)
    {
        GemmBatch gb{};
        gb.A[0] = uh;  gb.W[0] = wb2h; gb.C[0] = beta; gb.act[0] = 1; gb.oh[0] = 0;
        gb.A[1] = u2h; gb.W[1] = wg2h; gb.C[1] = gate; gb.act[1] = 2; gb.oh[1] = 0;
        gemm_fp16<<<dim3(E_/128, ROWS_/128, 2), blk, GEMM_SMEM>>>(gb, E_, R_);
    }

    householder_kernel<<<ROWS_, 256>>>(q, beta);

    gla_kernel<<<B_ * H_ * 16, 128>>>(q, k, v, fg, o);

    gateln_kernel<<<ROWS_, 256>>>(o, gate, gamma, t2h);

    // output projection (fp32 out)
    {
        GemmBatch gb{};
        gb.A[0] = t2h; gb.W[0] = woh; gb.C[0] = out; gb.act[0] = 0; gb.oh[0] = 0;
        gemm_fp16<<<dim3(E_/128, ROWS_/128, 1), blk, GEMM_SMEM>>>(gb, E_, E_);
    }
}